// round 1
// baseline (speedup 1.0000x reference)
#include <cuda_runtime.h>
#include <math.h>

#define Bb 64
#define Ll 12
#define Nn 4096
#define Cc 3
#define FDm 32
#define HDm 64
#define OUTD 12
#define TIDn 288
#define DIWn 7
#define TDm 16
#define NSTEPS 4
#define EMBm 10
#define BF (Bb*FDm)   // 2048 columns in node-major field layout

// Scratch (device globals: no allocation allowed in kernel_launch)
__device__ float g_A[(size_t)Nn*Nn];        // 64 MB  softmax(relu(E E^T))
__device__ float g_field[(size_t)Nn*BF];    // 32 MB  field[n][b*32+f]
__device__ float g_state[(size_t)Nn*BF];    // 32 MB
__device__ float g_AF[(size_t)Nn*BF];       // 32 MB  A @ field

// ---------------------------------------------------------------------------
// A = softmax(relu(node_emb @ node_emb^T), axis=-1). One block per row.
// ---------------------------------------------------------------------------
__global__ void __launch_bounds__(256) build_A(const float* __restrict__ emb) {
    int n = blockIdx.x;
    int tid = threadIdx.x;
    __shared__ float en[EMBm];
    __shared__ float red[256];
    if (tid < EMBm) en[tid] = emb[n*EMBm + tid];
    __syncthreads();
    float* row = g_A + (size_t)n * Nn;

    float lmax = 0.f;  // relu >= 0
    for (int m = tid; m < Nn; m += 256) {
        float d = 0.f;
        #pragma unroll
        for (int k = 0; k < EMBm; k++) d = fmaf(en[k], emb[m*EMBm + k], d);
        d = fmaxf(d, 0.f);
        row[m] = d;
        lmax = fmaxf(lmax, d);
    }
    red[tid] = lmax; __syncthreads();
    for (int s = 128; s > 0; s >>= 1) {
        if (tid < s) red[tid] = fmaxf(red[tid], red[tid+s]);
        __syncthreads();
    }
    float mx = red[0];
    __syncthreads();

    float lsum = 0.f;
    for (int m = tid; m < Nn; m += 256) {
        float e = expf(row[m] - mx);
        row[m] = e;
        lsum += e;
    }
    red[tid] = lsum; __syncthreads();
    for (int s = 128; s > 0; s >>= 1) {
        if (tid < s) red[tid] += red[tid+s];
        __syncthreads();
    }
    float inv = 1.f / red[0];
    __syncthreads();
    for (int m = tid; m < Nn; m += 256) row[m] *= inv;
}

// ---------------------------------------------------------------------------
// Encoder + temporal embedding. One warp per (b,n); lane = feature f.
// field[n][b*32+f] = relu(x @ enc_w1 + b1) @ enc_w2 + b2 + temp @ t2f_w + t2f_b
// ---------------------------------------------------------------------------
__global__ void __launch_bounds__(256) encoder_kernel(
    const float* __restrict__ hist,
    const float* __restrict__ tid_emb, const float* __restrict__ diw_emb,
    const float* __restrict__ t2f_w,   const float* __restrict__ t2f_b,
    const float* __restrict__ w1, const float* __restrict__ b1,
    const float* __restrict__ w2, const float* __restrict__ b2)
{
    __shared__ float s_w1[Ll*Cc*HDm];   // 36x64
    __shared__ float s_w2[HDm*FDm];     // 64x32
    __shared__ float s_t2f[2*TDm*FDm];  // 32x32
    __shared__ float s_b1[HDm];
    __shared__ float s_b2[FDm];
    __shared__ float s_t2fb[FDm];
    int tid = threadIdx.x;
    for (int i = tid; i < Ll*Cc*HDm; i += 256) s_w1[i] = w1[i];
    for (int i = tid; i < HDm*FDm;   i += 256) s_w2[i] = w2[i];
    for (int i = tid; i < 2*TDm*FDm; i += 256) s_t2f[i] = t2f_w[i];
    if (tid < HDm) s_b1[tid] = b1[tid];
    if (tid < FDm) { s_b2[tid] = b2[tid]; s_t2fb[tid] = t2f_b[tid]; }
    __syncthreads();

    int warp = (blockIdx.x * 256 + tid) >> 5;
    int lane = tid & 31;
    int n = warp & (Nn - 1);
    int b = warp >> 12;          // / 4096

    const float* hb = hist + ((size_t)b * Ll * Nn + n) * Cc;
    float x[Ll*Cc];
    #pragma unroll
    for (int l = 0; l < Ll; l++)
        #pragma unroll
        for (int c = 0; c < Cc; c++)
            x[l*Cc + c] = hb[(size_t)l * Nn * Cc + c];

    float h0 = s_b1[lane], h1 = s_b1[32 + lane];
    #pragma unroll
    for (int k = 0; k < Ll*Cc; k++) {
        h0 = fmaf(x[k], s_w1[k*HDm + lane],      h0);
        h1 = fmaf(x[k], s_w1[k*HDm + 32 + lane], h1);
    }
    h0 = fmaxf(h0, 0.f); h1 = fmaxf(h1, 0.f);

    float acc = s_b2[lane];
    #pragma unroll
    for (int hh = 0; hh < HDm; hh++) {
        float v = __shfl_sync(0xffffffffu, (hh < 32) ? h0 : h1, hh & 31);
        acc = fmaf(v, s_w2[hh*FDm + lane], acc);
    }

    // temporal embeddings from last timestep channels 1,2
    float v1 = hb[(size_t)(Ll-1)*Nn*Cc + 1];
    float v2 = hb[(size_t)(Ll-1)*Nn*Cc + 2];
    int ti = (int)(v1 * (float)TIDn); ti = min(max(ti, 0), TIDn-1);
    int di = (int)(v2 * (float)DIWn); di = min(max(di, 0), DIWn-1);
    #pragma unroll
    for (int k = 0; k < TDm; k++)
        acc = fmaf(tid_emb[ti*TDm + k], s_t2f[k*FDm + lane], acc);
    #pragma unroll
    for (int k = 0; k < TDm; k++)
        acc = fmaf(diw_emb[di*TDm + k], s_t2f[(TDm + k)*FDm + lane], acc);
    acc += s_t2fb[lane];

    g_field[(size_t)n * BF + b*FDm + lane] = acc;
}

// ---------------------------------------------------------------------------
// Big GEMM: g_AF[n][j] = sum_m g_A[n][m] * g_field[m][j]
// M=4096, N=2048, K=4096.  128x128x16 tile, 8x8 per thread, 256 threads.
// ---------------------------------------------------------------------------
#define GBM 128
#define GBN 128
#define GBK 16
__global__ void __launch_bounds__(256) gemm_AF()
{
    __shared__ float As[GBK][GBM];
    __shared__ float Bs[GBK][GBN];
    int tid  = threadIdx.x;
    int bcol = blockIdx.x;   // 0..15
    int brow = blockIdx.y;   // 0..31

    const float* Ab = g_A + (size_t)brow * GBM * Nn;
    const float* Fb = g_field + bcol * GBN;

    int a_r0 = tid >> 2;            // 0..63
    int a_c  = (tid & 3) * 4;       // 0,4,8,12
    int b_r0 = tid >> 5;            // 0..7
    int b_c  = (tid & 31) * 4;      // 0..124

    int tr = (tid >> 4) * 8;        // row offset in tile
    int tc = (tid & 15) * 8;        // col offset in tile

    float acc[8][8];
    #pragma unroll
    for (int i = 0; i < 8; i++)
        #pragma unroll
        for (int j = 0; j < 8; j++) acc[i][j] = 0.f;

    for (int k0 = 0; k0 < Nn; k0 += GBK) {
        #pragma unroll
        for (int rr = 0; rr < 2; rr++) {
            int m = a_r0 + rr*64;
            float4 v = *(const float4*)(Ab + (size_t)m*Nn + k0 + a_c);
            As[a_c+0][m] = v.x; As[a_c+1][m] = v.y;
            As[a_c+2][m] = v.z; As[a_c+3][m] = v.w;
        }
        #pragma unroll
        for (int rr = 0; rr < 2; rr++) {
            int k = b_r0 + rr*8;
            float4 v = *(const float4*)(Fb + (size_t)(k0+k)*BF + b_c);
            *(float4*)&Bs[k][b_c] = v;
        }
        __syncthreads();
        #pragma unroll
        for (int kk = 0; kk < GBK; kk++) {
            float ar[8], br[8];
            *(float4*)&ar[0] = *(float4*)&As[kk][tr];
            *(float4*)&ar[4] = *(float4*)&As[kk][tr+4];
            *(float4*)&br[0] = *(float4*)&Bs[kk][tc];
            *(float4*)&br[4] = *(float4*)&Bs[kk][tc+4];
            #pragma unroll
            for (int i = 0; i < 8; i++)
                #pragma unroll
                for (int j = 0; j < 8; j++)
                    acc[i][j] = fmaf(ar[i], br[j], acc[i][j]);
        }
        __syncthreads();
    }

    float* Cb = g_AF + (size_t)(brow*GBM + tr) * BF + bcol*GBN + tc;
    #pragma unroll
    for (int i = 0; i < 8; i++) {
        *(float4*)(Cb + (size_t)i*BF)     = *(float4*)&acc[i][0];
        *(float4*)(Cb + (size_t)i*BF + 4) = *(float4*)&acc[i][4];
    }
}

// ---------------------------------------------------------------------------
// Per-step pointwise + small MLPs. One warp per (b,n); lane = feature f.
// ---------------------------------------------------------------------------
__global__ void __launch_bounds__(256) step_kernel(
    const float* __restrict__ pw1, const float* __restrict__ pb1,
    const float* __restrict__ pw2, const float* __restrict__ pb2,
    const float* __restrict__ win, const float* __restrict__ wst,
    const float* __restrict__ sb,  const float* __restrict__ wout,
    const float* __restrict__ bout, const float* __restrict__ pde_mix,
    int first)
{
    __shared__ float s_w1[FDm*HDm], s_w2[HDm*FDm];
    __shared__ float s_win[FDm*FDm], s_wst[FDm*FDm], s_wout[FDm*FDm];
    __shared__ float s_b1[HDm], s_b2[FDm], s_sb[FDm], s_bout[FDm];
    int tid = threadIdx.x;
    for (int i = tid; i < FDm*HDm; i += 256) { s_w1[i] = pw1[i]; s_w2[i] = pw2[i]; }
    for (int i = tid; i < FDm*FDm; i += 256) { s_win[i] = win[i]; s_wst[i] = wst[i]; s_wout[i] = wout[i]; }
    if (tid < HDm) s_b1[tid] = pb1[tid];
    if (tid < FDm) { s_b2[tid] = pb2[tid]; s_sb[tid] = sb[tid]; s_bout[tid] = bout[tid]; }
    __syncthreads();

    float alpha = 1.f / (1.f + expf(-pde_mix[0]));
    const float dtc = 1.f / NSTEPS;

    int warp = (blockIdx.x * 256 + tid) >> 5;
    int lane = tid & 31;
    int b = warp & 63;
    int n = warp >> 6;
    size_t off = (size_t)n * BF + b*FDm + lane;

    float fld = g_field[off];
    float af  = g_AF[off];
    float st  = first ? 0.f : g_state[off];

    // N_F = relu(field @ pde_w1 + b1) @ pde_w2 + b2
    float h0 = s_b1[lane], h1 = s_b1[32 + lane];
    #pragma unroll
    for (int k = 0; k < FDm; k++) {
        float fk = __shfl_sync(0xffffffffu, fld, k);
        h0 = fmaf(fk, s_w1[k*HDm + lane],      h0);
        h1 = fmaf(fk, s_w1[k*HDm + 32 + lane], h1);
    }
    h0 = fmaxf(h0, 0.f); h1 = fmaxf(h1, 0.f);
    float nf = s_b2[lane];
    #pragma unroll
    for (int hh = 0; hh < HDm; hh++) {
        float v = __shfl_sync(0xffffffffu, (hh < 32) ? h0 : h1, hh & 31);
        nf = fmaf(v, s_w2[hh*FDm + lane], nf);
    }

    float lf = af - fld;
    float fe = fld + (alpha*lf + (1.f - alpha)*nf) * dtc;

    // state = tanh(fe @ ss_win + state @ ss_wst + ss_b)
    float sacc = s_sb[lane];
    #pragma unroll
    for (int k = 0; k < FDm; k++) {
        float fek = __shfl_sync(0xffffffffu, fe, k);
        float stk = __shfl_sync(0xffffffffu, st, k);
        sacc = fmaf(fek, s_win[k*FDm + lane], sacc);
        sacc = fmaf(stk, s_wst[k*FDm + lane], sacc);
    }
    float stn = tanhf(sacc);

    // field = fe + state_new @ ss_wout + ss_bout
    float fout = fe + s_bout[lane];
    #pragma unroll
    for (int k = 0; k < FDm; k++) {
        float sk = __shfl_sync(0xffffffffu, stn, k);
        fout = fmaf(sk, s_wout[k*FDm + lane], fout);
    }

    g_state[off] = stn;
    g_field[off] = fout;
}

// ---------------------------------------------------------------------------
// Decoder. One warp per (b,n). out[(b*12+o)*4096 + n]
// ---------------------------------------------------------------------------
__global__ void __launch_bounds__(256) decoder_kernel(
    const float* __restrict__ w1, const float* __restrict__ b1,
    const float* __restrict__ w2, const float* __restrict__ b2,
    float* __restrict__ out)
{
    __shared__ float s_w1[FDm*HDm], s_w2[HDm*OUTD];
    __shared__ float s_b1[HDm], s_b2[OUTD];
    int tid = threadIdx.x;
    for (int i = tid; i < FDm*HDm;  i += 256) s_w1[i] = w1[i];
    for (int i = tid; i < HDm*OUTD; i += 256) s_w2[i] = w2[i];
    if (tid < HDm) s_b1[tid] = b1[tid];
    if (tid < OUTD) s_b2[tid] = b2[tid];
    __syncthreads();

    int warp = (blockIdx.x * 256 + tid) >> 5;
    int lane = tid & 31;
    int b = warp & 63;
    int n = warp >> 6;

    float fld = g_field[(size_t)n * BF + b*FDm + lane];
    float h0 = s_b1[lane], h1 = s_b1[32 + lane];
    #pragma unroll
    for (int k = 0; k < FDm; k++) {
        float fk = __shfl_sync(0xffffffffu, fld, k);
        h0 = fmaf(fk, s_w1[k*HDm + lane],      h0);
        h1 = fmaf(fk, s_w1[k*HDm + 32 + lane], h1);
    }
    h0 = fmaxf(h0, 0.f); h1 = fmaxf(h1, 0.f);

    float o = (lane < OUTD) ? s_b2[lane] : 0.f;
    #pragma unroll
    for (int hh = 0; hh < HDm; hh++) {
        float v = __shfl_sync(0xffffffffu, (hh < 32) ? h0 : h1, hh & 31);
        if (lane < OUTD) o = fmaf(v, s_w2[hh*OUTD + lane], o);
    }
    if (lane < OUTD)
        out[((size_t)b*OUTD + lane)*Nn + n] = o;
}

// ---------------------------------------------------------------------------
extern "C" void kernel_launch(void* const* d_in, const int* in_sizes, int n_in,
                              void* d_out, int out_size)
{
    const float* hist     = (const float*)d_in[0];
    // d_in[1]=future_data, d_in[2..4]=batch_seen/epoch/train (unused)
    const float* tid_emb  = (const float*)d_in[5];
    const float* diw_emb  = (const float*)d_in[6];
    const float* t2f_w    = (const float*)d_in[7];
    const float* t2f_b    = (const float*)d_in[8];
    const float* enc_w1   = (const float*)d_in[9];
    const float* enc_b1   = (const float*)d_in[10];
    const float* enc_w2   = (const float*)d_in[11];
    const float* enc_b2   = (const float*)d_in[12];
    const float* node_emb = (const float*)d_in[13];
    const float* pde_w1   = (const float*)d_in[14];
    const float* pde_b1   = (const float*)d_in[15];
    const float* pde_w2   = (const float*)d_in[16];
    const float* pde_b2   = (const float*)d_in[17];
    const float* ss_win   = (const float*)d_in[18];
    const float* ss_wst   = (const float*)d_in[19];
    const float* ss_b     = (const float*)d_in[20];
    const float* ss_wout  = (const float*)d_in[21];
    const float* ss_bout  = (const float*)d_in[22];
    const float* dec_w1   = (const float*)d_in[23];
    const float* dec_b1   = (const float*)d_in[24];
    const float* dec_w2   = (const float*)d_in[25];
    const float* dec_b2   = (const float*)d_in[26];
    const float* pde_mix  = (const float*)d_in[27];

    build_A<<<Nn, 256>>>(node_emb);

    encoder_kernel<<<(Bb*Nn)/8, 256>>>(hist, tid_emb, diw_emb, t2f_w, t2f_b,
                                       enc_w1, enc_b1, enc_w2, enc_b2);

    for (int s = 0; s < NSTEPS; s++) {
        gemm_AF<<<dim3(BF/GBN, Nn/GBM), 256>>>();
        step_kernel<<<(Bb*Nn)/8, 256>>>(pde_w1, pde_b1, pde_w2, pde_b2,
                                        ss_win, ss_wst, ss_b, ss_wout, ss_bout,
                                        pde_mix, s == 0);
    }

    decoder_kernel<<<(Bb*Nn)/8, 256>>>(dec_w1, dec_b1, dec_w2, dec_b2,
                                       (float*)d_out);
}

// round 2
// speedup vs baseline: 1.0096x; 1.0096x over previous
#include <cuda_runtime.h>
#include <math.h>

#define Bb 64
#define Ll 12
#define Nn 4096
#define Cc 3
#define FDm 32
#define HDm 64
#define OUTD 12
#define TIDn 288
#define DIWn 7
#define TDm 16
#define NSTEPS 4
#define EMBm 10
#define BF (Bb*FDm)   // 2048 columns in node-major field layout

// Scratch (device globals: no allocation allowed in kernel_launch)
__device__ float g_A[(size_t)Nn*Nn];        // 64 MB  softmax(relu(E E^T))
__device__ float g_field[(size_t)Nn*BF];    // 32 MB  field[n][b*32+f]
__device__ float g_state[(size_t)Nn*BF];    // 32 MB
__device__ float g_AF[(size_t)Nn*BF];       // 32 MB  A @ field

// packed f32x2 helpers
#define FMA2(d,a,b) asm("fma.rn.f32x2 %0, %1, %2, %0;" : "+l"(d) : "l"(a), "l"(b))
#define PK2(d,lo,hi) asm("mov.b64 %0, {%1, %2};" : "=l"(d) : "r"(lo), "r"(hi))

// ---------------------------------------------------------------------------
// A = softmax(relu(node_emb @ node_emb^T), axis=-1). One block per row.
// ---------------------------------------------------------------------------
__global__ void __launch_bounds__(256) build_A(const float* __restrict__ emb) {
    int n = blockIdx.x;
    int tid = threadIdx.x;
    __shared__ float en[EMBm];
    __shared__ float red[256];
    if (tid < EMBm) en[tid] = emb[n*EMBm + tid];
    __syncthreads();
    float* row = g_A + (size_t)n * Nn;

    float lmax = 0.f;  // relu >= 0
    for (int m = tid; m < Nn; m += 256) {
        float d = 0.f;
        #pragma unroll
        for (int k = 0; k < EMBm; k++) d = fmaf(en[k], emb[m*EMBm + k], d);
        d = fmaxf(d, 0.f);
        row[m] = d;
        lmax = fmaxf(lmax, d);
    }
    red[tid] = lmax; __syncthreads();
    for (int s = 128; s > 0; s >>= 1) {
        if (tid < s) red[tid] = fmaxf(red[tid], red[tid+s]);
        __syncthreads();
    }
    float mx = red[0];
    __syncthreads();

    float lsum = 0.f;
    for (int m = tid; m < Nn; m += 256) {
        float e = expf(row[m] - mx);
        row[m] = e;
        lsum += e;
    }
    red[tid] = lsum; __syncthreads();
    for (int s = 128; s > 0; s >>= 1) {
        if (tid < s) red[tid] += red[tid+s];
        __syncthreads();
    }
    float inv = 1.f / red[0];
    __syncthreads();
    for (int m = tid; m < Nn; m += 256) row[m] *= inv;
}

// ---------------------------------------------------------------------------
// Encoder + temporal embedding. One warp per (b,n); lane = feature f.
// ---------------------------------------------------------------------------
__global__ void __launch_bounds__(256) encoder_kernel(
    const float* __restrict__ hist,
    const float* __restrict__ tid_emb, const float* __restrict__ diw_emb,
    const float* __restrict__ t2f_w,   const float* __restrict__ t2f_b,
    const float* __restrict__ w1, const float* __restrict__ b1,
    const float* __restrict__ w2, const float* __restrict__ b2)
{
    __shared__ float s_w1[Ll*Cc*HDm];   // 36x64
    __shared__ float s_w2[HDm*FDm];     // 64x32
    __shared__ float s_t2f[2*TDm*FDm];  // 32x32
    __shared__ float s_b1[HDm];
    __shared__ float s_b2[FDm];
    __shared__ float s_t2fb[FDm];
    int tid = threadIdx.x;
    for (int i = tid; i < Ll*Cc*HDm; i += 256) s_w1[i] = w1[i];
    for (int i = tid; i < HDm*FDm;   i += 256) s_w2[i] = w2[i];
    for (int i = tid; i < 2*TDm*FDm; i += 256) s_t2f[i] = t2f_w[i];
    if (tid < HDm) s_b1[tid] = b1[tid];
    if (tid < FDm) { s_b2[tid] = b2[tid]; s_t2fb[tid] = t2f_b[tid]; }
    __syncthreads();

    int warp = (blockIdx.x * 256 + tid) >> 5;
    int lane = tid & 31;
    int n = warp & (Nn - 1);
    int b = warp >> 12;          // / 4096

    const float* hb = hist + ((size_t)b * Ll * Nn + n) * Cc;
    float x[Ll*Cc];
    #pragma unroll
    for (int l = 0; l < Ll; l++)
        #pragma unroll
        for (int c = 0; c < Cc; c++)
            x[l*Cc + c] = hb[(size_t)l * Nn * Cc + c];

    float h0 = s_b1[lane], h1 = s_b1[32 + lane];
    #pragma unroll
    for (int k = 0; k < Ll*Cc; k++) {
        h0 = fmaf(x[k], s_w1[k*HDm + lane],      h0);
        h1 = fmaf(x[k], s_w1[k*HDm + 32 + lane], h1);
    }
    h0 = fmaxf(h0, 0.f); h1 = fmaxf(h1, 0.f);

    float acc = s_b2[lane];
    #pragma unroll
    for (int hh = 0; hh < HDm; hh++) {
        float v = __shfl_sync(0xffffffffu, (hh < 32) ? h0 : h1, hh & 31);
        acc = fmaf(v, s_w2[hh*FDm + lane], acc);
    }

    float v1 = hb[(size_t)(Ll-1)*Nn*Cc + 1];
    float v2 = hb[(size_t)(Ll-1)*Nn*Cc + 2];
    int ti = (int)(v1 * (float)TIDn); ti = min(max(ti, 0), TIDn-1);
    int di = (int)(v2 * (float)DIWn); di = min(max(di, 0), DIWn-1);
    #pragma unroll
    for (int k = 0; k < TDm; k++)
        acc = fmaf(tid_emb[ti*TDm + k], s_t2f[k*FDm + lane], acc);
    #pragma unroll
    for (int k = 0; k < TDm; k++)
        acc = fmaf(diw_emb[di*TDm + k], s_t2f[(TDm + k)*FDm + lane], acc);
    acc += s_t2fb[lane];

    g_field[(size_t)n * BF + b*FDm + lane] = acc;
}

// ---------------------------------------------------------------------------
// Big GEMM: g_AF[n][j] = sum_m g_A[n][m] * g_field[m][j]
// M=4096, N=2048, K=4096.  128x128x16 tile, 8x8 per thread, 256 threads.
// Inner loop uses packed fma.rn.f32x2 (FFMA2): 2 FLOPs per FMA issue slot.
// ---------------------------------------------------------------------------
#define GBM 128
#define GBN 128
#define GBK 16
__global__ void __launch_bounds__(256, 2) gemm_AF()
{
    __shared__ __align__(16) float As[GBK][GBM];
    __shared__ __align__(16) float Bs[GBK][GBN];
    int tid  = threadIdx.x;
    int bcol = blockIdx.x;   // 0..15
    int brow = blockIdx.y;   // 0..31

    const float* Ab = g_A + (size_t)brow * GBM * Nn;
    const float* Fb = g_field + bcol * GBN;

    int a_r0 = tid >> 2;            // 0..63
    int a_c  = (tid & 3) * 4;       // 0,4,8,12
    int b_r0 = tid >> 5;            // 0..7
    int b_c  = (tid & 31) * 4;      // 0..124

    int tr = (tid >> 4) * 8;        // row offset in tile
    int tc = (tid & 15) * 8;        // col offset in tile

    unsigned long long acc2[8][4];  // acc2[i][j] = cols {tc+2j, tc+2j+1} of row tr+i
    #pragma unroll
    for (int i = 0; i < 8; i++)
        #pragma unroll
        for (int j = 0; j < 4; j++) acc2[i][j] = 0ull;

    for (int k0 = 0; k0 < Nn; k0 += GBK) {
        #pragma unroll
        for (int rr = 0; rr < 2; rr++) {
            int m = a_r0 + rr*64;
            float4 v = *(const float4*)(Ab + (size_t)m*Nn + k0 + a_c);
            As[a_c+0][m] = v.x; As[a_c+1][m] = v.y;
            As[a_c+2][m] = v.z; As[a_c+3][m] = v.w;
        }
        #pragma unroll
        for (int rr = 0; rr < 2; rr++) {
            int k = b_r0 + rr*8;
            float4 v = *(const float4*)(Fb + (size_t)(k0+k)*BF + b_c);
            *(float4*)&Bs[k][b_c] = v;
        }
        __syncthreads();
        #pragma unroll
        for (int kk = 0; kk < GBK; kk++) {
            float4 av0 = *(const float4*)&As[kk][tr];
            float4 av1 = *(const float4*)&As[kk][tr+4];
            ulonglong2 bv0 = *(const ulonglong2*)&Bs[kk][tc];
            ulonglong2 bv1 = *(const ulonglong2*)&Bs[kk][tc+4];
            unsigned long long b2[4] = {bv0.x, bv0.y, bv1.x, bv1.y};
            float ar[8] = {av0.x, av0.y, av0.z, av0.w, av1.x, av1.y, av1.z, av1.w};
            unsigned long long a2[8];
            #pragma unroll
            for (int i = 0; i < 8; i++) {
                unsigned int u = __float_as_uint(ar[i]);
                PK2(a2[i], u, u);
            }
            #pragma unroll
            for (int i = 0; i < 8; i++)
                #pragma unroll
                for (int j = 0; j < 4; j++)
                    FMA2(acc2[i][j], a2[i], b2[j]);
        }
        __syncthreads();
    }

    float* Cb = g_AF + (size_t)(brow*GBM + tr) * BF + bcol*GBN + tc;
    #pragma unroll
    for (int i = 0; i < 8; i++)
        #pragma unroll
        for (int j = 0; j < 4; j++)
            *(unsigned long long*)(Cb + (size_t)i*BF + 2*j) = acc2[i][j];
}

// ---------------------------------------------------------------------------
// Per-step pointwise + small MLPs. One warp per (b,n); lane = feature f.
// ---------------------------------------------------------------------------
__global__ void __launch_bounds__(256) step_kernel(
    const float* __restrict__ pw1, const float* __restrict__ pb1,
    const float* __restrict__ pw2, const float* __restrict__ pb2,
    const float* __restrict__ win, const float* __restrict__ wst,
    const float* __restrict__ sb,  const float* __restrict__ wout,
    const float* __restrict__ bout, const float* __restrict__ pde_mix,
    int first)
{
    __shared__ float s_w1[FDm*HDm], s_w2[HDm*FDm];
    __shared__ float s_win[FDm*FDm], s_wst[FDm*FDm], s_wout[FDm*FDm];
    __shared__ float s_b1[HDm], s_b2[FDm], s_sb[FDm], s_bout[FDm];
    int tid = threadIdx.x;
    for (int i = tid; i < FDm*HDm; i += 256) { s_w1[i] = pw1[i]; s_w2[i] = pw2[i]; }
    for (int i = tid; i < FDm*FDm; i += 256) { s_win[i] = win[i]; s_wst[i] = wst[i]; s_wout[i] = wout[i]; }
    if (tid < HDm) s_b1[tid] = pb1[tid];
    if (tid < FDm) { s_b2[tid] = pb2[tid]; s_sb[tid] = sb[tid]; s_bout[tid] = bout[tid]; }
    __syncthreads();

    float alpha = 1.f / (1.f + expf(-pde_mix[0]));
    const float dtc = 1.f / NSTEPS;

    int warp = (blockIdx.x * 256 + tid) >> 5;
    int lane = tid & 31;
    int b = warp & 63;
    int n = warp >> 6;
    size_t off = (size_t)n * BF + b*FDm + lane;

    float fld = g_field[off];
    float af  = g_AF[off];
    float st  = first ? 0.f : g_state[off];

    float h0 = s_b1[lane], h1 = s_b1[32 + lane];
    #pragma unroll
    for (int k = 0; k < FDm; k++) {
        float fk = __shfl_sync(0xffffffffu, fld, k);
        h0 = fmaf(fk, s_w1[k*HDm + lane],      h0);
        h1 = fmaf(fk, s_w1[k*HDm + 32 + lane], h1);
    }
    h0 = fmaxf(h0, 0.f); h1 = fmaxf(h1, 0.f);
    float nf = s_b2[lane];
    #pragma unroll
    for (int hh = 0; hh < HDm; hh++) {
        float v = __shfl_sync(0xffffffffu, (hh < 32) ? h0 : h1, hh & 31);
        nf = fmaf(v, s_w2[hh*FDm + lane], nf);
    }

    float lf = af - fld;
    float fe = fld + (alpha*lf + (1.f - alpha)*nf) * dtc;

    float sacc = s_sb[lane];
    #pragma unroll
    for (int k = 0; k < FDm; k++) {
        float fek = __shfl_sync(0xffffffffu, fe, k);
        float stk = __shfl_sync(0xffffffffu, st, k);
        sacc = fmaf(fek, s_win[k*FDm + lane], sacc);
        sacc = fmaf(stk, s_wst[k*FDm + lane], sacc);
    }
    float stn = tanhf(sacc);

    float fout = fe + s_bout[lane];
    #pragma unroll
    for (int k = 0; k < FDm; k++) {
        float sk = __shfl_sync(0xffffffffu, stn, k);
        fout = fmaf(sk, s_wout[k*FDm + lane], fout);
    }

    g_state[off] = stn;
    g_field[off] = fout;
}

// ---------------------------------------------------------------------------
// Decoder. One warp per (b,n). out[(b*12+o)*4096 + n]
// ---------------------------------------------------------------------------
__global__ void __launch_bounds__(256) decoder_kernel(
    const float* __restrict__ w1, const float* __restrict__ b1,
    const float* __restrict__ w2, const float* __restrict__ b2,
    float* __restrict__ out)
{
    __shared__ float s_w1[FDm*HDm], s_w2[HDm*OUTD];
    __shared__ float s_b1[HDm], s_b2[OUTD];
    int tid = threadIdx.x;
    for (int i = tid; i < FDm*HDm;  i += 256) s_w1[i] = w1[i];
    for (int i = tid; i < HDm*OUTD; i += 256) s_w2[i] = w2[i];
    if (tid < HDm) s_b1[tid] = b1[tid];
    if (tid < OUTD) s_b2[tid] = b2[tid];
    __syncthreads();

    int warp = (blockIdx.x * 256 + tid) >> 5;
    int lane = tid & 31;
    int b = warp & 63;
    int n = warp >> 6;

    float fld = g_field[(size_t)n * BF + b*FDm + lane];
    float h0 = s_b1[lane], h1 = s_b1[32 + lane];
    #pragma unroll
    for (int k = 0; k < FDm; k++) {
        float fk = __shfl_sync(0xffffffffu, fld, k);
        h0 = fmaf(fk, s_w1[k*HDm + lane],      h0);
        h1 = fmaf(fk, s_w1[k*HDm + 32 + lane], h1);
    }
    h0 = fmaxf(h0, 0.f); h1 = fmaxf(h1, 0.f);

    float o = (lane < OUTD) ? s_b2[lane] : 0.f;
    #pragma unroll
    for (int hh = 0; hh < HDm; hh++) {
        float v = __shfl_sync(0xffffffffu, (hh < 32) ? h0 : h1, hh & 31);
        if (lane < OUTD) o = fmaf(v, s_w2[hh*OUTD + lane], o);
    }
    if (lane < OUTD)
        out[((size_t)b*OUTD + lane)*Nn + n] = o;
}

// ---------------------------------------------------------------------------
extern "C" void kernel_launch(void* const* d_in, const int* in_sizes, int n_in,
                              void* d_out, int out_size)
{
    const float* hist     = (const float*)d_in[0];
    const float* tid_emb  = (const float*)d_in[5];
    const float* diw_emb  = (const float*)d_in[6];
    const float* t2f_w    = (const float*)d_in[7];
    const float* t2f_b    = (const float*)d_in[8];
    const float* enc_w1   = (const float*)d_in[9];
    const float* enc_b1   = (const float*)d_in[10];
    const float* enc_w2   = (const float*)d_in[11];
    const float* enc_b2   = (const float*)d_in[12];
    const float* node_emb = (const float*)d_in[13];
    const float* pde_w1   = (const float*)d_in[14];
    const float* pde_b1   = (const float*)d_in[15];
    const float* pde_w2   = (const float*)d_in[16];
    const float* pde_b2   = (const float*)d_in[17];
    const float* ss_win   = (const float*)d_in[18];
    const float* ss_wst   = (const float*)d_in[19];
    const float* ss_b     = (const float*)d_in[20];
    const float* ss_wout  = (const float*)d_in[21];
    const float* ss_bout  = (const float*)d_in[22];
    const float* dec_w1   = (const float*)d_in[23];
    const float* dec_b1   = (const float*)d_in[24];
    const float* dec_w2   = (const float*)d_in[25];
    const float* dec_b2   = (const float*)d_in[26];
    const float* pde_mix  = (const float*)d_in[27];

    build_A<<<Nn, 256>>>(node_emb);

    encoder_kernel<<<(Bb*Nn)/8, 256>>>(hist, tid_emb, diw_emb, t2f_w, t2f_b,
                                       enc_w1, enc_b1, enc_w2, enc_b2);

    for (int s = 0; s < NSTEPS; s++) {
        gemm_AF<<<dim3(BF/GBN, Nn/GBM), 256>>>();
        step_kernel<<<(Bb*Nn)/8, 256>>>(pde_w1, pde_b1, pde_w2, pde_b2,
                                        ss_win, ss_wst, ss_b, ss_wout, ss_bout,
                                        pde_mix, s == 0);
    }

    decoder_kernel<<<(Bb*Nn)/8, 256>>>(dec_w1, dec_b1, dec_w2, dec_b2,
                                       (float*)d_out);
}

// round 4
// speedup vs baseline: 1.6630x; 1.6472x over previous
#include <cuda_runtime.h>
#include <cuda_bf16.h>
#include <math.h>
#include <cstdint>

#define Bb 64
#define Ll 12
#define Nn 4096
#define Cc 3
#define FDm 32
#define HDm 64
#define OUTD 12
#define TIDn 288
#define DIWn 7
#define TDm 16
#define NSTEPS 4
#define EMBm 10
#define BF (Bb*FDm)   // 2048

// Scratch (device globals)
__device__ float g_A[(size_t)Nn*Nn];                              // softmax scratch
__device__ float g_field[(size_t)Nn*BF];                          // field[n][b*32+f]
__device__ float g_state[(size_t)Nn*BF];
__device__ float g_AF[(size_t)Nn*BF];                             // A @ field (fp32)
__device__ __align__(16) __nv_bfloat16 g_Ahi[(size_t)Nn*Nn];      // A hi split [n][m]
__device__ __align__(16) __nv_bfloat16 g_Alo[(size_t)Nn*Nn];      // A lo split
__device__ __align__(16) __nv_bfloat16 g_FThi[(size_t)BF*Nn];     // fieldT hi [j][m]
__device__ __align__(16) __nv_bfloat16 g_FTlo[(size_t)BF*Nn];     // fieldT lo

// ------------------------------ PTX helpers -------------------------------
__device__ __forceinline__ uint32_t smem_to_u32(const void* p) {
    uint32_t a;
    asm("{ .reg .u64 t; cvta.to.shared.u64 t, %1; cvt.u32.u64 %0, t; }"
        : "=r"(a) : "l"(p));
    return a;
}
__device__ __forceinline__ void cp16(uint32_t dst, const void* src) {
    asm volatile("cp.async.cg.shared.global [%0], [%1], 16;" :: "r"(dst), "l"(src));
}
#define CP_COMMIT() asm volatile("cp.async.commit_group;" ::: "memory")
#define CP_WAIT(n)  asm volatile("cp.async.wait_group %0;" :: "n"(n) : "memory")

__device__ __forceinline__ void ldsm4(uint32_t* r, uint32_t addr) {
    asm volatile("ldmatrix.sync.aligned.m8n8.x4.shared.b16 {%0,%1,%2,%3}, [%4];"
                 : "=r"(r[0]), "=r"(r[1]), "=r"(r[2]), "=r"(r[3]) : "r"(addr));
}
__device__ __forceinline__ void mma_bf16(float* c, const uint32_t* a, const uint32_t* b) {
    asm volatile("mma.sync.aligned.m16n8k16.row.col.f32.bf16.bf16.f32 "
                 "{%0,%1,%2,%3}, {%4,%5,%6,%7}, {%8,%9}, {%0,%1,%2,%3};"
                 : "+f"(c[0]), "+f"(c[1]), "+f"(c[2]), "+f"(c[3])
                 : "r"(a[0]), "r"(a[1]), "r"(a[2]), "r"(a[3]), "r"(b[0]), "r"(b[1]));
}

// ---------------------------------------------------------------------------
// A = softmax(relu(node_emb @ node_emb^T)); writes bf16 hi/lo split.
// ---------------------------------------------------------------------------
__global__ void __launch_bounds__(256) build_A(const float* __restrict__ emb) {
    int n = blockIdx.x;
    int tid = threadIdx.x;
    __shared__ float en[EMBm];
    __shared__ float red[256];
    if (tid < EMBm) en[tid] = emb[n*EMBm + tid];
    __syncthreads();
    float* row = g_A + (size_t)n * Nn;

    float lmax = 0.f;
    for (int m = tid; m < Nn; m += 256) {
        float d = 0.f;
        #pragma unroll
        for (int k = 0; k < EMBm; k++) d = fmaf(en[k], emb[m*EMBm + k], d);
        d = fmaxf(d, 0.f);
        row[m] = d;
        lmax = fmaxf(lmax, d);
    }
    red[tid] = lmax; __syncthreads();
    for (int s = 128; s > 0; s >>= 1) {
        if (tid < s) red[tid] = fmaxf(red[tid], red[tid+s]);
        __syncthreads();
    }
    float mx = red[0];
    __syncthreads();

    float lsum = 0.f;
    for (int m = tid; m < Nn; m += 256) {
        float e = expf(row[m] - mx);
        row[m] = e;
        lsum += e;
    }
    red[tid] = lsum; __syncthreads();
    for (int s = 128; s > 0; s >>= 1) {
        if (tid < s) red[tid] += red[tid+s];
        __syncthreads();
    }
    float inv = 1.f / red[0];
    __syncthreads();
    for (int m = tid; m < Nn; m += 256) {
        float v = row[m] * inv;
        __nv_bfloat16 h = __float2bfloat16_rn(v);
        float lo = v - __bfloat162float(h);
        g_Ahi[(size_t)n*Nn + m] = h;
        g_Alo[(size_t)n*Nn + m] = __float2bfloat16_rn(lo);
    }
}

// ---------------------------------------------------------------------------
// Transpose + bf16-split field: FT[j][m] = field[m][j]
// ---------------------------------------------------------------------------
__global__ void __launch_bounds__(256) split_field_T() {
    __shared__ float t[32][33];
    int j0 = blockIdx.x * 32;
    int n0 = blockIdx.y * 32;
    int tx = threadIdx.x & 31, ty = threadIdx.x >> 5;   // 32 x 8
    #pragma unroll
    for (int r = 0; r < 32; r += 8)
        t[ty + r][tx] = g_field[(size_t)(n0 + ty + r) * BF + j0 + tx];
    __syncthreads();
    #pragma unroll
    for (int r = 0; r < 32; r += 8) {
        float v = t[tx][ty + r];
        __nv_bfloat16 h = __float2bfloat16_rn(v);
        float lo = v - __bfloat162float(h);
        size_t off = (size_t)(j0 + ty + r) * Nn + n0 + tx;
        g_FThi[off] = h;
        g_FTlo[off] = __float2bfloat16_rn(lo);
    }
}

// ---------------------------------------------------------------------------
// Encoder + temporal embedding. One warp per (b,n).
// ---------------------------------------------------------------------------
__global__ void __launch_bounds__(256) encoder_kernel(
    const float* __restrict__ hist,
    const float* __restrict__ tid_emb, const float* __restrict__ diw_emb,
    const float* __restrict__ t2f_w,   const float* __restrict__ t2f_b,
    const float* __restrict__ w1, const float* __restrict__ b1,
    const float* __restrict__ w2, const float* __restrict__ b2)
{
    __shared__ float s_w1[Ll*Cc*HDm];
    __shared__ float s_w2[HDm*FDm];
    __shared__ float s_t2f[2*TDm*FDm];
    __shared__ float s_b1[HDm];
    __shared__ float s_b2[FDm];
    __shared__ float s_t2fb[FDm];
    int tid = threadIdx.x;
    for (int i = tid; i < Ll*Cc*HDm; i += 256) s_w1[i] = w1[i];
    for (int i = tid; i < HDm*FDm;   i += 256) s_w2[i] = w2[i];
    for (int i = tid; i < 2*TDm*FDm; i += 256) s_t2f[i] = t2f_w[i];
    if (tid < HDm) s_b1[tid] = b1[tid];
    if (tid < FDm) { s_b2[tid] = b2[tid]; s_t2fb[tid] = t2f_b[tid]; }
    __syncthreads();

    int warp = (blockIdx.x * 256 + tid) >> 5;
    int lane = tid & 31;
    int n = warp & (Nn - 1);
    int b = warp >> 12;

    const float* hb = hist + ((size_t)b * Ll * Nn + n) * Cc;
    float x[Ll*Cc];
    #pragma unroll
    for (int l = 0; l < Ll; l++)
        #pragma unroll
        for (int c = 0; c < Cc; c++)
            x[l*Cc + c] = hb[(size_t)l * Nn * Cc + c];

    float h0 = s_b1[lane], h1 = s_b1[32 + lane];
    #pragma unroll
    for (int k = 0; k < Ll*Cc; k++) {
        h0 = fmaf(x[k], s_w1[k*HDm + lane],      h0);
        h1 = fmaf(x[k], s_w1[k*HDm + 32 + lane], h1);
    }
    h0 = fmaxf(h0, 0.f); h1 = fmaxf(h1, 0.f);

    float acc = s_b2[lane];
    #pragma unroll
    for (int hh = 0; hh < HDm; hh++) {
        float v = __shfl_sync(0xffffffffu, (hh < 32) ? h0 : h1, hh & 31);
        acc = fmaf(v, s_w2[hh*FDm + lane], acc);
    }

    float v1 = hb[(size_t)(Ll-1)*Nn*Cc + 1];
    float v2 = hb[(size_t)(Ll-1)*Nn*Cc + 2];
    int ti = (int)(v1 * (float)TIDn); ti = min(max(ti, 0), TIDn-1);
    int di = (int)(v2 * (float)DIWn); di = min(max(di, 0), DIWn-1);
    #pragma unroll
    for (int k = 0; k < TDm; k++)
        acc = fmaf(tid_emb[ti*TDm + k], s_t2f[k*FDm + lane], acc);
    #pragma unroll
    for (int k = 0; k < TDm; k++)
        acc = fmaf(diw_emb[di*TDm + k], s_t2f[(TDm + k)*FDm + lane], acc);
    acc += s_t2fb[lane];

    g_field[(size_t)n * BF + b*FDm + lane] = acc;
}

// ---------------------------------------------------------------------------
// Split-bf16 tensor-core GEMM via mma.sync: g_AF = A @ field
// M=4096, N=2048, K=4096. CTA 128x128xBK32, 8 warps (2x4), warp tile 64x32.
// D += Ahi*Bhi + Alo*Bhi + Ahi*Blo (fp32 accumulators)
// ---------------------------------------------------------------------------
#define BKg 32
#define LDAe 40                       // padded row stride (bf16 elems) = 80 B
#define TILE_BYTES (128*LDAe*2)       // 10240
#define STAGE_BYTES (4*TILE_BYTES)    // 40960 (Ahi,Alo,Bhi,Blo)
#define GSMEM (2*STAGE_BYTES)         // 81920

__global__ void __launch_bounds__(256) gemm_mma()
{
    extern __shared__ char smem[];
    uint32_t sbase = smem_to_u32(smem);
    int tid = threadIdx.x;
    int lane = tid & 31;
    int wid = tid >> 5;
    int bcol = blockIdx.x;    // 0..15
    int brow = blockIdx.y;    // 0..31

    const __nv_bfloat16* Ahi = g_Ahi + (size_t)brow * 128 * Nn;
    const __nv_bfloat16* Alo = g_Alo + (size_t)brow * 128 * Nn;
    const __nv_bfloat16* Bhi = g_FThi + (size_t)bcol * 128 * Nn;
    const __nv_bfloat16* Blo = g_FTlo + (size_t)bcol * 128 * Nn;

    // loader: thread t covers row r = t/2, 16-elem chunk c = (t&1)*16
    int lr = tid >> 1;
    int lc = (tid & 1) * 16;
    size_t goff = (size_t)lr * Nn + lc;
    uint32_t sdst = sbase + lr * (LDAe*2) + lc * 2;

    int warp_m = wid & 1;     // 2 rows of warps
    int warp_n = wid >> 1;    // 4 cols of warps
    int m_base = warp_m * 64;
    int n_base = warp_n * 32;

    float acc[4][4][4];
    #pragma unroll
    for (int i = 0; i < 4; i++)
        #pragma unroll
        for (int j = 0; j < 4; j++)
            #pragma unroll
            for (int q = 0; q < 4; q++) acc[i][j][q] = 0.f;

    // precompute ldmatrix intra-tile byte offsets (kk added at use site)
    // A atom i: row = m_base + i*16 + (lane&15), col8 = (lane>>4)*8
    uint32_t a_off[4];
    #pragma unroll
    for (int i = 0; i < 4; i++)
        a_off[i] = (m_base + i*16 + (lane & 15)) * (LDAe*2) + ((lane >> 4) * 8) * 2;
    // B pair j: row = n_base + j*16 + ((lane>>4)<<3) + (lane&7), col8 = ((lane>>3)&1)*8
    uint32_t b_off[2];
    #pragma unroll
    for (int j = 0; j < 2; j++)
        b_off[j] = (n_base + j*16 + ((lane >> 4) << 3) + (lane & 7)) * (LDAe*2)
                 + (((lane >> 3) & 1) * 8) * 2;

    // stage 0 prefetch
    {
        uint32_t d = sdst;
        cp16(d,                  Ahi + goff); cp16(d + 16,                Ahi + goff + 8);
        cp16(d + TILE_BYTES,     Alo + goff); cp16(d + TILE_BYTES + 16,   Alo + goff + 8);
        cp16(d + 2*TILE_BYTES,   Bhi + goff); cp16(d + 2*TILE_BYTES + 16, Bhi + goff + 8);
        cp16(d + 3*TILE_BYTES,   Blo + goff); cp16(d + 3*TILE_BYTES + 16, Blo + goff + 8);
        CP_COMMIT();
    }

    const int NIT = Nn / BKg;   // 128
    for (int it = 0; it < NIT; it++) {
        if (it + 1 < NIT) {
            uint32_t d = sdst + ((it + 1) & 1) * STAGE_BYTES;
            size_t g = goff + (size_t)(it + 1) * BKg;
            cp16(d,                  Ahi + g); cp16(d + 16,                Ahi + g + 8);
            cp16(d + TILE_BYTES,     Alo + g); cp16(d + TILE_BYTES + 16,   Alo + g + 8);
            cp16(d + 2*TILE_BYTES,   Bhi + g); cp16(d + 2*TILE_BYTES + 16, Bhi + g + 8);
            cp16(d + 3*TILE_BYTES,   Blo + g); cp16(d + 3*TILE_BYTES + 16, Blo + g + 8);
            CP_COMMIT();
            CP_WAIT(1);
        } else {
            CP_WAIT(0);
        }
        __syncthreads();

        uint32_t st = sbase + (it & 1) * STAGE_BYTES;
        #pragma unroll
        for (int kk = 0; kk < 2; kk++) {          // two k16 steps per BK=32
            uint32_t koff = kk * 16 * 2;
            uint32_t ahif[4][4], alof[4][4];
            #pragma unroll
            for (int i = 0; i < 4; i++) {
                uint32_t ad = st + a_off[i] + koff;
                ldsm4(ahif[i], ad);
                ldsm4(alof[i], ad + TILE_BYTES);
            }
            uint32_t bhif[2][4], blof[2][4];
            #pragma unroll
            for (int j = 0; j < 2; j++) {
                uint32_t bd = st + 2*TILE_BYTES + b_off[j] + koff;
                ldsm4(bhif[j], bd);
                ldsm4(blof[j], bd + TILE_BYTES);
            }
            #pragma unroll
            for (int i = 0; i < 4; i++)
                #pragma unroll
                for (int na = 0; na < 4; na++) {
                    const uint32_t* bh = &bhif[na >> 1][(na & 1) * 2];
                    const uint32_t* bl = &blof[na >> 1][(na & 1) * 2];
                    mma_bf16(acc[i][na], ahif[i], bh);
                    mma_bf16(acc[i][na], alof[i], bh);
                    mma_bf16(acc[i][na], ahif[i], bl);
                }
        }
        __syncthreads();
    }

    // epilogue: fragment layout -> g_AF
    int grow0 = brow * 128 + m_base + (lane >> 2);
    int gcol0 = bcol * 128 + n_base + 2 * (lane & 3);
    #pragma unroll
    for (int i = 0; i < 4; i++) {
        #pragma unroll
        for (int na = 0; na < 4; na++) {
            float* p0 = g_AF + (size_t)(grow0 + i*16)     * BF + gcol0 + na*8;
            float* p1 = g_AF + (size_t)(grow0 + i*16 + 8) * BF + gcol0 + na*8;
            *(float2*)p0 = make_float2(acc[i][na][0], acc[i][na][1]);
            *(float2*)p1 = make_float2(acc[i][na][2], acc[i][na][3]);
        }
    }
}

// ---------------------------------------------------------------------------
// Per-step pointwise + small MLPs. One warp per (b,n).
// ---------------------------------------------------------------------------
__global__ void __launch_bounds__(256) step_kernel(
    const float* __restrict__ pw1, const float* __restrict__ pb1,
    const float* __restrict__ pw2, const float* __restrict__ pb2,
    const float* __restrict__ win, const float* __restrict__ wst,
    const float* __restrict__ sb,  const float* __restrict__ wout,
    const float* __restrict__ bout, const float* __restrict__ pde_mix,
    int first)
{
    __shared__ float s_w1[FDm*HDm], s_w2[HDm*FDm];
    __shared__ float s_win[FDm*FDm], s_wst[FDm*FDm], s_wout[FDm*FDm];
    __shared__ float s_b1[HDm], s_b2[FDm], s_sb[FDm], s_bout[FDm];
    int tid = threadIdx.x;
    for (int i = tid; i < FDm*HDm; i += 256) { s_w1[i] = pw1[i]; s_w2[i] = pw2[i]; }
    for (int i = tid; i < FDm*FDm; i += 256) { s_win[i] = win[i]; s_wst[i] = wst[i]; s_wout[i] = wout[i]; }
    if (tid < HDm) s_b1[tid] = pb1[tid];
    if (tid < FDm) { s_b2[tid] = pb2[tid]; s_sb[tid] = sb[tid]; s_bout[tid] = bout[tid]; }
    __syncthreads();

    float alpha = 1.f / (1.f + expf(-pde_mix[0]));
    const float dtc = 1.f / NSTEPS;

    int warp = (blockIdx.x * 256 + tid) >> 5;
    int lane = tid & 31;
    int b = warp & 63;
    int n = warp >> 6;
    size_t off = (size_t)n * BF + b*FDm + lane;

    float fld = g_field[off];
    float af  = g_AF[off];
    float st  = first ? 0.f : g_state[off];

    float h0 = s_b1[lane], h1 = s_b1[32 + lane];
    #pragma unroll
    for (int k = 0; k < FDm; k++) {
        float fk = __shfl_sync(0xffffffffu, fld, k);
        h0 = fmaf(fk, s_w1[k*HDm + lane],      h0);
        h1 = fmaf(fk, s_w1[k*HDm + 32 + lane], h1);
    }
    h0 = fmaxf(h0, 0.f); h1 = fmaxf(h1, 0.f);
    float nf = s_b2[lane];
    #pragma unroll
    for (int hh = 0; hh < HDm; hh++) {
        float v = __shfl_sync(0xffffffffu, (hh < 32) ? h0 : h1, hh & 31);
        nf = fmaf(v, s_w2[hh*FDm + lane], nf);
    }

    float lf = af - fld;
    float fe = fld + (alpha*lf + (1.f - alpha)*nf) * dtc;

    float sacc = s_sb[lane];
    #pragma unroll
    for (int k = 0; k < FDm; k++) {
        float fek = __shfl_sync(0xffffffffu, fe, k);
        float stk = __shfl_sync(0xffffffffu, st, k);
        sacc = fmaf(fek, s_win[k*FDm + lane], sacc);
        sacc = fmaf(stk, s_wst[k*FDm + lane], sacc);
    }
    float stn = tanhf(sacc);

    float fout = fe + s_bout[lane];
    #pragma unroll
    for (int k = 0; k < FDm; k++) {
        float sk = __shfl_sync(0xffffffffu, stn, k);
        fout = fmaf(sk, s_wout[k*FDm + lane], fout);
    }

    g_state[off] = stn;
    g_field[off] = fout;
}

// ---------------------------------------------------------------------------
// Decoder. One warp per (b,n). out[(b*12+o)*4096 + n]
// ---------------------------------------------------------------------------
__global__ void __launch_bounds__(256) decoder_kernel(
    const float* __restrict__ w1, const float* __restrict__ b1,
    const float* __restrict__ w2, const float* __restrict__ b2,
    float* __restrict__ out)
{
    __shared__ float s_w1[FDm*HDm], s_w2[HDm*OUTD];
    __shared__ float s_b1[HDm], s_b2[OUTD];
    int tid = threadIdx.x;
    for (int i = tid; i < FDm*HDm;  i += 256) s_w1[i] = w1[i];
    for (int i = tid; i < HDm*OUTD; i += 256) s_w2[i] = w2[i];
    if (tid < HDm) s_b1[tid] = b1[tid];
    if (tid < OUTD) s_b2[tid] = b2[tid];
    __syncthreads();

    int warp = (blockIdx.x * 256 + tid) >> 5;
    int lane = tid & 31;
    int b = warp & 63;
    int n = warp >> 6;

    float fld = g_field[(size_t)n * BF + b*FDm + lane];
    float h0 = s_b1[lane], h1 = s_b1[32 + lane];
    #pragma unroll
    for (int k = 0; k < FDm; k++) {
        float fk = __shfl_sync(0xffffffffu, fld, k);
        h0 = fmaf(fk, s_w1[k*HDm + lane],      h0);
        h1 = fmaf(fk, s_w1[k*HDm + 32 + lane], h1);
    }
    h0 = fmaxf(h0, 0.f); h1 = fmaxf(h1, 0.f);

    float o = (lane < OUTD) ? s_b2[lane] : 0.f;
    #pragma unroll
    for (int hh = 0; hh < HDm; hh++) {
        float v = __shfl_sync(0xffffffffu, (hh < 32) ? h0 : h1, hh & 31);
        if (lane < OUTD) o = fmaf(v, s_w2[hh*OUTD + lane], o);
    }
    if (lane < OUTD)
        out[((size_t)b*OUTD + lane)*Nn + n] = o;
}

// ---------------------------------------------------------------------------
extern "C" void kernel_launch(void* const* d_in, const int* in_sizes, int n_in,
                              void* d_out, int out_size)
{
    const float* hist     = (const float*)d_in[0];
    const float* tid_emb  = (const float*)d_in[5];
    const float* diw_emb  = (const float*)d_in[6];
    const float* t2f_w    = (const float*)d_in[7];
    const float* t2f_b    = (const float*)d_in[8];
    const float* enc_w1   = (const float*)d_in[9];
    const float* enc_b1   = (const float*)d_in[10];
    const float* enc_w2   = (const float*)d_in[11];
    const float* enc_b2   = (const float*)d_in[12];
    const float* node_emb = (const float*)d_in[13];
    const float* pde_w1   = (const float*)d_in[14];
    const float* pde_b1   = (const float*)d_in[15];
    const float* pde_w2   = (const float*)d_in[16];
    const float* pde_b2   = (const float*)d_in[17];
    const float* ss_win   = (const float*)d_in[18];
    const float* ss_wst   = (const float*)d_in[19];
    const float* ss_b     = (const float*)d_in[20];
    const float* ss_wout  = (const float*)d_in[21];
    const float* ss_bout  = (const float*)d_in[22];
    const float* dec_w1   = (const float*)d_in[23];
    const float* dec_b1   = (const float*)d_in[24];
    const float* dec_w2   = (const float*)d_in[25];
    const float* dec_b2   = (const float*)d_in[26];
    const float* pde_mix  = (const float*)d_in[27];

    static int smem_set = 0;
    if (!smem_set) {
        cudaFuncSetAttribute(gemm_mma, cudaFuncAttributeMaxDynamicSharedMemorySize, GSMEM);
        smem_set = 1;
    }

    build_A<<<Nn, 256>>>(node_emb);

    encoder_kernel<<<(Bb*Nn)/8, 256>>>(hist, tid_emb, diw_emb, t2f_w, t2f_b,
                                       enc_w1, enc_b1, enc_w2, enc_b2);

    for (int s = 0; s < NSTEPS; s++) {
        split_field_T<<<dim3(BF/32, Nn/32), 256>>>();
        gemm_mma<<<dim3(BF/128, Nn/128), 256, GSMEM>>>();
        step_kernel<<<(Bb*Nn)/8, 256>>>(pde_w1, pde_b1, pde_w2, pde_b2,
                                        ss_win, ss_wst, ss_b, ss_wout, ss_bout,
                                        pde_mix, s == 0);
    }

    decoder_kernel<<<(Bb*Nn)/8, 256>>>(dec_w1, dec_b1, dec_w2, dec_b2,
                                       (float*)d_out);
}

// round 5
// speedup vs baseline: 2.0646x; 1.2415x over previous
#include <cuda_runtime.h>
#include <cuda_bf16.h>
#include <math.h>
#include <cstdint>

#define Bb 64
#define Ll 12
#define Nn 4096
#define Cc 3
#define FDm 32
#define HDm 64
#define OUTD 12
#define TIDn 288
#define DIWn 7
#define TDm 16
#define NSTEPS 4
#define EMBm 10
#define BF (Bb*FDm)   // 2048

// Scratch (device globals)
__device__ float g_A[(size_t)Nn*Nn];                              // softmax scratch
__device__ float g_field[(size_t)Nn*BF];                          // field[n][b*32+f]
__device__ float g_state[(size_t)Nn*BF];
__device__ float g_AF[(size_t)Nn*BF];                             // A @ field (fp32)
__device__ __align__(16) __nv_bfloat16 g_Ahi[(size_t)Nn*Nn];      // A hi split [n][m]
__device__ __align__(16) __nv_bfloat16 g_Alo[(size_t)Nn*Nn];      // A lo split
__device__ __align__(16) __nv_bfloat16 g_FThi[(size_t)BF*Nn];     // fieldT hi [j][m]
__device__ __align__(16) __nv_bfloat16 g_FTlo[(size_t)BF*Nn];     // fieldT lo

// ------------------------------ PTX helpers -------------------------------
__device__ __forceinline__ uint32_t smem_to_u32(const void* p) {
    uint32_t a;
    asm("{ .reg .u64 t; cvta.to.shared.u64 t, %1; cvt.u32.u64 %0, t; }"
        : "=r"(a) : "l"(p));
    return a;
}
__device__ __forceinline__ void cp16(uint32_t dst, const void* src) {
    asm volatile("cp.async.cg.shared.global [%0], [%1], 16;" :: "r"(dst), "l"(src));
}
#define CP_COMMIT() asm volatile("cp.async.commit_group;" ::: "memory")
#define CP_WAIT(n)  asm volatile("cp.async.wait_group %0;" :: "n"(n) : "memory")

__device__ __forceinline__ void ldsm4(uint32_t* r, uint32_t addr) {
    asm volatile("ldmatrix.sync.aligned.m8n8.x4.shared.b16 {%0,%1,%2,%3}, [%4];"
                 : "=r"(r[0]), "=r"(r[1]), "=r"(r[2]), "=r"(r[3]) : "r"(addr));
}
__device__ __forceinline__ void mma_bf16(float* c, const uint32_t* a, const uint32_t* b) {
    asm volatile("mma.sync.aligned.m16n8k16.row.col.f32.bf16.bf16.f32 "
                 "{%0,%1,%2,%3}, {%4,%5,%6,%7}, {%8,%9}, {%0,%1,%2,%3};"
                 : "+f"(c[0]), "+f"(c[1]), "+f"(c[2]), "+f"(c[3])
                 : "r"(a[0]), "r"(a[1]), "r"(a[2]), "r"(a[3]), "r"(b[0]), "r"(b[1]));
}

// ---------------------------------------------------------------------------
// A = softmax(relu(node_emb @ node_emb^T)); writes bf16 hi/lo split.
// ---------------------------------------------------------------------------
__global__ void __launch_bounds__(256) build_A(const float* __restrict__ emb) {
    int n = blockIdx.x;
    int tid = threadIdx.x;
    __shared__ float en[EMBm];
    __shared__ float red[256];
    if (tid < EMBm) en[tid] = emb[n*EMBm + tid];
    __syncthreads();
    float* row = g_A + (size_t)n * Nn;

    float lmax = 0.f;
    for (int m = tid; m < Nn; m += 256) {
        float d = 0.f;
        #pragma unroll
        for (int k = 0; k < EMBm; k++) d = fmaf(en[k], emb[m*EMBm + k], d);
        d = fmaxf(d, 0.f);
        row[m] = d;
        lmax = fmaxf(lmax, d);
    }
    red[tid] = lmax; __syncthreads();
    for (int s = 128; s > 0; s >>= 1) {
        if (tid < s) red[tid] = fmaxf(red[tid], red[tid+s]);
        __syncthreads();
    }
    float mx = red[0];
    __syncthreads();

    float lsum = 0.f;
    for (int m = tid; m < Nn; m += 256) {
        float e = expf(row[m] - mx);
        row[m] = e;
        lsum += e;
    }
    red[tid] = lsum; __syncthreads();
    for (int s = 128; s > 0; s >>= 1) {
        if (tid < s) red[tid] += red[tid+s];
        __syncthreads();
    }
    float inv = 1.f / red[0];
    __syncthreads();
    for (int m = tid; m < Nn; m += 256) {
        float v = row[m] * inv;
        __nv_bfloat16 h = __float2bfloat16_rn(v);
        float lo = v - __bfloat162float(h);
        g_Ahi[(size_t)n*Nn + m] = h;
        g_Alo[(size_t)n*Nn + m] = __float2bfloat16_rn(lo);
    }
}

// ---------------------------------------------------------------------------
// Transpose + bf16-split field: FT[j][m] = field[m][j]
// ---------------------------------------------------------------------------
__global__ void __launch_bounds__(256) split_field_T() {
    __shared__ float t[32][33];
    int j0 = blockIdx.x * 32;
    int n0 = blockIdx.y * 32;
    int tx = threadIdx.x & 31, ty = threadIdx.x >> 5;   // 32 x 8
    #pragma unroll
    for (int r = 0; r < 32; r += 8)
        t[ty + r][tx] = g_field[(size_t)(n0 + ty + r) * BF + j0 + tx];
    __syncthreads();
    #pragma unroll
    for (int r = 0; r < 32; r += 8) {
        float v = t[tx][ty + r];
        __nv_bfloat16 h = __float2bfloat16_rn(v);
        float lo = v - __bfloat162float(h);
        size_t off = (size_t)(j0 + ty + r) * Nn + n0 + tx;
        g_FThi[off] = h;
        g_FTlo[off] = __float2bfloat16_rn(lo);
    }
}

// ---------------------------------------------------------------------------
// Encoder + temporal embedding. One warp per (b,n).
// ---------------------------------------------------------------------------
__global__ void __launch_bounds__(256) encoder_kernel(
    const float* __restrict__ hist,
    const float* __restrict__ tid_emb, const float* __restrict__ diw_emb,
    const float* __restrict__ t2f_w,   const float* __restrict__ t2f_b,
    const float* __restrict__ w1, const float* __restrict__ b1,
    const float* __restrict__ w2, const float* __restrict__ b2)
{
    __shared__ float s_w1[Ll*Cc*HDm];
    __shared__ float s_w2[HDm*FDm];
    __shared__ float s_t2f[2*TDm*FDm];
    __shared__ float s_b1[HDm];
    __shared__ float s_b2[FDm];
    __shared__ float s_t2fb[FDm];
    int tid = threadIdx.x;
    for (int i = tid; i < Ll*Cc*HDm; i += 256) s_w1[i] = w1[i];
    for (int i = tid; i < HDm*FDm;   i += 256) s_w2[i] = w2[i];
    for (int i = tid; i < 2*TDm*FDm; i += 256) s_t2f[i] = t2f_w[i];
    if (tid < HDm) s_b1[tid] = b1[tid];
    if (tid < FDm) { s_b2[tid] = b2[tid]; s_t2fb[tid] = t2f_b[tid]; }
    __syncthreads();

    int warp = (blockIdx.x * 256 + tid) >> 5;
    int lane = tid & 31;
    int n = warp & (Nn - 1);
    int b = warp >> 12;

    const float* hb = hist + ((size_t)b * Ll * Nn + n) * Cc;
    float x[Ll*Cc];
    #pragma unroll
    for (int l = 0; l < Ll; l++)
        #pragma unroll
        for (int c = 0; c < Cc; c++)
            x[l*Cc + c] = hb[(size_t)l * Nn * Cc + c];

    float h0 = s_b1[lane], h1 = s_b1[32 + lane];
    #pragma unroll
    for (int k = 0; k < Ll*Cc; k++) {
        h0 = fmaf(x[k], s_w1[k*HDm + lane],      h0);
        h1 = fmaf(x[k], s_w1[k*HDm + 32 + lane], h1);
    }
    h0 = fmaxf(h0, 0.f); h1 = fmaxf(h1, 0.f);

    float acc = s_b2[lane];
    #pragma unroll
    for (int hh = 0; hh < HDm; hh++) {
        float v = __shfl_sync(0xffffffffu, (hh < 32) ? h0 : h1, hh & 31);
        acc = fmaf(v, s_w2[hh*FDm + lane], acc);
    }

    float v1 = hb[(size_t)(Ll-1)*Nn*Cc + 1];
    float v2 = hb[(size_t)(Ll-1)*Nn*Cc + 2];
    int ti = (int)(v1 * (float)TIDn); ti = min(max(ti, 0), TIDn-1);
    int di = (int)(v2 * (float)DIWn); di = min(max(di, 0), DIWn-1);
    #pragma unroll
    for (int k = 0; k < TDm; k++)
        acc = fmaf(tid_emb[ti*TDm + k], s_t2f[k*FDm + lane], acc);
    #pragma unroll
    for (int k = 0; k < TDm; k++)
        acc = fmaf(diw_emb[di*TDm + k], s_t2f[(TDm + k)*FDm + lane], acc);
    acc += s_t2fb[lane];

    g_field[(size_t)n * BF + b*FDm + lane] = acc;
}

// ---------------------------------------------------------------------------
// Split-bf16 tensor-core GEMM via mma.sync: g_AF = A @ field
// M=4096, N=2048, K=4096. CTA 128x128xBK32, 8 warps (2x4), warp tile 64x32.
// D += Ahi*Bhi + Alo*Bhi + Ahi*Blo (fp32 accumulators). 2 CTAs/SM.
// ---------------------------------------------------------------------------
#define BKg 32
#define LDAe 40                       // padded row stride (bf16 elems) = 80 B
#define TILE_BYTES (128*LDAe*2)       // 10240
#define STAGE_BYTES (4*TILE_BYTES)    // 40960 (Ahi,Alo,Bhi,Blo)
#define GSMEM (2*STAGE_BYTES)         // 81920

__global__ void __launch_bounds__(256, 2) gemm_mma()
{
    extern __shared__ char smem[];
    uint32_t sbase = smem_to_u32(smem);
    int tid = threadIdx.x;
    int lane = tid & 31;
    int wid = tid >> 5;
    int bcol = blockIdx.x;    // 0..15
    int brow = blockIdx.y;    // 0..31

    const __nv_bfloat16* Ahi = g_Ahi + (size_t)brow * 128 * Nn;
    const __nv_bfloat16* Alo = g_Alo + (size_t)brow * 128 * Nn;
    const __nv_bfloat16* Bhi = g_FThi + (size_t)bcol * 128 * Nn;
    const __nv_bfloat16* Blo = g_FTlo + (size_t)bcol * 128 * Nn;

    // loader: thread t covers row r = t/2, 16-elem chunk c = (t&1)*16
    int lr = tid >> 1;
    int lc = (tid & 1) * 16;
    size_t goff = (size_t)lr * Nn + lc;
    uint32_t sdst = sbase + lr * (LDAe*2) + lc * 2;

    int warp_m = wid & 1;     // 2 rows of warps
    int warp_n = wid >> 1;    // 4 cols of warps
    int m_base = warp_m * 64;
    int n_base = warp_n * 32;

    float acc[4][4][4];
    #pragma unroll
    for (int i = 0; i < 4; i++)
        #pragma unroll
        for (int j = 0; j < 4; j++)
            #pragma unroll
            for (int q = 0; q < 4; q++) acc[i][j][q] = 0.f;

    uint32_t a_off[4];
    #pragma unroll
    for (int i = 0; i < 4; i++)
        a_off[i] = (m_base + i*16 + (lane & 15)) * (LDAe*2) + ((lane >> 4) * 8) * 2;
    uint32_t b_off[2];
    #pragma unroll
    for (int j = 0; j < 2; j++)
        b_off[j] = (n_base + j*16 + ((lane >> 4) << 3) + (lane & 7)) * (LDAe*2)
                 + (((lane >> 3) & 1) * 8) * 2;

    // stage 0 prefetch
    {
        uint32_t d = sdst;
        cp16(d,                  Ahi + goff); cp16(d + 16,                Ahi + goff + 8);
        cp16(d + TILE_BYTES,     Alo + goff); cp16(d + TILE_BYTES + 16,   Alo + goff + 8);
        cp16(d + 2*TILE_BYTES,   Bhi + goff); cp16(d + 2*TILE_BYTES + 16, Bhi + goff + 8);
        cp16(d + 3*TILE_BYTES,   Blo + goff); cp16(d + 3*TILE_BYTES + 16, Blo + goff + 8);
        CP_COMMIT();
    }

    const int NIT = Nn / BKg;   // 128
    for (int it = 0; it < NIT; it++) {
        if (it + 1 < NIT) {
            uint32_t d = sdst + ((it + 1) & 1) * STAGE_BYTES;
            size_t g = goff + (size_t)(it + 1) * BKg;
            cp16(d,                  Ahi + g); cp16(d + 16,                Ahi + g + 8);
            cp16(d + TILE_BYTES,     Alo + g); cp16(d + TILE_BYTES + 16,   Alo + g + 8);
            cp16(d + 2*TILE_BYTES,   Bhi + g); cp16(d + 2*TILE_BYTES + 16, Bhi + g + 8);
            cp16(d + 3*TILE_BYTES,   Blo + g); cp16(d + 3*TILE_BYTES + 16, Blo + g + 8);
            CP_COMMIT();
            CP_WAIT(1);
        } else {
            CP_WAIT(0);
        }
        __syncthreads();

        uint32_t st = sbase + (it & 1) * STAGE_BYTES;
        #pragma unroll
        for (int kk = 0; kk < 2; kk++) {
            uint32_t koff = kk * 16 * 2;
            uint32_t ahif[4][4], alof[4][4];
            #pragma unroll
            for (int i = 0; i < 4; i++) {
                uint32_t ad = st + a_off[i] + koff;
                ldsm4(ahif[i], ad);
                ldsm4(alof[i], ad + TILE_BYTES);
            }
            uint32_t bhif[2][4], blof[2][4];
            #pragma unroll
            for (int j = 0; j < 2; j++) {
                uint32_t bd = st + 2*TILE_BYTES + b_off[j] + koff;
                ldsm4(bhif[j], bd);
                ldsm4(blof[j], bd + TILE_BYTES);
            }
            #pragma unroll
            for (int i = 0; i < 4; i++)
                #pragma unroll
                for (int na = 0; na < 4; na++) {
                    const uint32_t* bh = &bhif[na >> 1][(na & 1) * 2];
                    const uint32_t* bl = &blof[na >> 1][(na & 1) * 2];
                    mma_bf16(acc[i][na], ahif[i], bh);
                    mma_bf16(acc[i][na], alof[i], bh);
                    mma_bf16(acc[i][na], ahif[i], bl);
                }
        }
        __syncthreads();
    }

    int grow0 = brow * 128 + m_base + (lane >> 2);
    int gcol0 = bcol * 128 + n_base + 2 * (lane & 3);
    #pragma unroll
    for (int i = 0; i < 4; i++) {
        #pragma unroll
        for (int na = 0; na < 4; na++) {
            float* p0 = g_AF + (size_t)(grow0 + i*16)     * BF + gcol0 + na*8;
            float* p1 = g_AF + (size_t)(grow0 + i*16 + 8) * BF + gcol0 + na*8;
            *(float2*)p0 = make_float2(acc[i][na][0], acc[i][na][1]);
            *(float2*)p1 = make_float2(acc[i][na][2], acc[i][na][3]);
        }
    }
}

// ---------------------------------------------------------------------------
// Per-step pointwise + small MLPs. THREAD-per-point: thread owns all 32
// features of point p=(n*64+b); row at g_field+p*32 is contiguous.
// No shuffles; weights broadcast from SMEM.
// ---------------------------------------------------------------------------
__global__ void __launch_bounds__(256) step_kernel(
    const float* __restrict__ pw1, const float* __restrict__ pb1,
    const float* __restrict__ pw2, const float* __restrict__ pb2,
    const float* __restrict__ win, const float* __restrict__ wst,
    const float* __restrict__ sb,  const float* __restrict__ wout,
    const float* __restrict__ bout, const float* __restrict__ pde_mix,
    int first)
{
    __shared__ float s_w1[FDm*HDm], s_w2[HDm*FDm];
    __shared__ float s_win[FDm*FDm], s_wst[FDm*FDm], s_wout[FDm*FDm];
    __shared__ float s_b1[HDm], s_b2[FDm], s_sb[FDm], s_bout[FDm];
    int tid = threadIdx.x;
    for (int i = tid; i < FDm*HDm; i += 256) { s_w1[i] = pw1[i]; s_w2[i] = pw2[i]; }
    for (int i = tid; i < FDm*FDm; i += 256) { s_win[i] = win[i]; s_wst[i] = wst[i]; s_wout[i] = wout[i]; }
    if (tid < HDm) s_b1[tid] = pb1[tid];
    if (tid < FDm) { s_b2[tid] = pb2[tid]; s_sb[tid] = sb[tid]; s_bout[tid] = bout[tid]; }
    __syncthreads();

    float alpha = 1.f / (1.f + expf(-pde_mix[0]));
    const float dtc = 1.f / NSTEPS;

    size_t p = (size_t)blockIdx.x * 256 + tid;     // 0..262143
    float* fbase = g_field + p * FDm;
    const float* abase = g_AF + p * FDm;
    float* sbase_g = g_state + p * FDm;

    float x[FDm];
    #pragma unroll
    for (int i = 0; i < FDm/4; i++) *(float4*)&x[i*4] = *(const float4*)(fbase + i*4);

    // h = relu(x @ W1 + b1)
    float h[HDm];
    #pragma unroll
    for (int hh = 0; hh < HDm; hh++) h[hh] = s_b1[hh];
    #pragma unroll
    for (int k = 0; k < FDm; k++) {
        float xk = x[k];
        #pragma unroll
        for (int hh = 0; hh < HDm; hh++)
            h[hh] = fmaf(xk, s_w1[k*HDm + hh], h[hh]);
    }
    #pragma unroll
    for (int hh = 0; hh < HDm; hh++) h[hh] = fmaxf(h[hh], 0.f);

    // nf = h @ W2 + b2
    float nf[FDm];
    #pragma unroll
    for (int f = 0; f < FDm; f++) nf[f] = s_b2[f];
    #pragma unroll
    for (int hh = 0; hh < HDm; hh++) {
        float hv = h[hh];
        #pragma unroll
        for (int f = 0; f < FDm; f++)
            nf[f] = fmaf(hv, s_w2[hh*FDm + f], nf[f]);
    }

    // fe = x + (alpha*(af - x) + (1-alpha)*nf)*dt
    float fe[FDm];
    #pragma unroll
    for (int i = 0; i < FDm/4; i++) {
        float4 af4 = *(const float4*)(abase + i*4);
        float afv[4] = {af4.x, af4.y, af4.z, af4.w};
        #pragma unroll
        for (int q = 0; q < 4; q++) {
            int f = i*4 + q;
            fe[f] = x[f] + (alpha*(afv[q] - x[f]) + (1.f - alpha)*nf[f]) * dtc;
        }
    }

    // st_in
    float st[FDm];
    if (first) {
        #pragma unroll
        for (int f = 0; f < FDm; f++) st[f] = 0.f;
    } else {
        #pragma unroll
        for (int i = 0; i < FDm/4; i++) *(float4*)&st[i*4] = *(const float4*)(sbase_g + i*4);
    }

    // sa = fe @ win + st @ wst + sb ; stn = tanh(sa)
    float sa[FDm];
    #pragma unroll
    for (int f = 0; f < FDm; f++) sa[f] = s_sb[f];
    #pragma unroll
    for (int k = 0; k < FDm; k++) {
        float fk = fe[k], sk = st[k];
        #pragma unroll
        for (int f = 0; f < FDm; f++) {
            sa[f] = fmaf(fk, s_win[k*FDm + f], sa[f]);
            sa[f] = fmaf(sk, s_wst[k*FDm + f], sa[f]);
        }
    }
    float stn[FDm];
    #pragma unroll
    for (int f = 0; f < FDm; f++) stn[f] = tanhf(sa[f]);
    #pragma unroll
    for (int i = 0; i < FDm/4; i++) *(float4*)(sbase_g + i*4) = *(float4*)&stn[i*4];

    // fout = fe + stn @ wout + bout
    float fout[FDm];
    #pragma unroll
    for (int f = 0; f < FDm; f++) fout[f] = fe[f] + s_bout[f];
    #pragma unroll
    for (int k = 0; k < FDm; k++) {
        float sk = stn[k];
        #pragma unroll
        for (int f = 0; f < FDm; f++)
            fout[f] = fmaf(sk, s_wout[k*FDm + f], fout[f]);
    }
    #pragma unroll
    for (int i = 0; i < FDm/4; i++) *(float4*)(fbase + i*4) = *(float4*)&fout[i*4];
}

// ---------------------------------------------------------------------------
// Decoder. One warp per (b,n). out[(b*12+o)*4096 + n]
// ---------------------------------------------------------------------------
__global__ void __launch_bounds__(256) decoder_kernel(
    const float* __restrict__ w1, const float* __restrict__ b1,
    const float* __restrict__ w2, const float* __restrict__ b2,
    float* __restrict__ out)
{
    __shared__ float s_w1[FDm*HDm], s_w2[HDm*OUTD];
    __shared__ float s_b1[HDm], s_b2[OUTD];
    int tid = threadIdx.x;
    for (int i = tid; i < FDm*HDm;  i += 256) s_w1[i] = w1[i];
    for (int i = tid; i < HDm*OUTD; i += 256) s_w2[i] = w2[i];
    if (tid < HDm) s_b1[tid] = b1[tid];
    if (tid < OUTD) s_b2[tid] = b2[tid];
    __syncthreads();

    int warp = (blockIdx.x * 256 + tid) >> 5;
    int lane = tid & 31;
    int b = warp & 63;
    int n = warp >> 6;

    float fld = g_field[(size_t)n * BF + b*FDm + lane];
    float h0 = s_b1[lane], h1 = s_b1[32 + lane];
    #pragma unroll
    for (int k = 0; k < FDm; k++) {
        float fk = __shfl_sync(0xffffffffu, fld, k);
        h0 = fmaf(fk, s_w1[k*HDm + lane],      h0);
        h1 = fmaf(fk, s_w1[k*HDm + 32 + lane], h1);
    }
    h0 = fmaxf(h0, 0.f); h1 = fmaxf(h1, 0.f);

    float o = (lane < OUTD) ? s_b2[lane] : 0.f;
    #pragma unroll
    for (int hh = 0; hh < HDm; hh++) {
        float v = __shfl_sync(0xffffffffu, (hh < 32) ? h0 : h1, hh & 31);
        if (lane < OUTD) o = fmaf(v, s_w2[hh*OUTD + lane], o);
    }
    if (lane < OUTD)
        out[((size_t)b*OUTD + lane)*Nn + n] = o;
}

// ---------------------------------------------------------------------------
extern "C" void kernel_launch(void* const* d_in, const int* in_sizes, int n_in,
                              void* d_out, int out_size)
{
    const float* hist     = (const float*)d_in[0];
    const float* tid_emb  = (const float*)d_in[5];
    const float* diw_emb  = (const float*)d_in[6];
    const float* t2f_w    = (const float*)d_in[7];
    const float* t2f_b    = (const float*)d_in[8];
    const float* enc_w1   = (const float*)d_in[9];
    const float* enc_b1   = (const float*)d_in[10];
    const float* enc_w2   = (const float*)d_in[11];
    const float* enc_b2   = (const float*)d_in[12];
    const float* node_emb = (const float*)d_in[13];
    const float* pde_w1   = (const float*)d_in[14];
    const float* pde_b1   = (const float*)d_in[15];
    const float* pde_w2   = (const float*)d_in[16];
    const float* pde_b2   = (const float*)d_in[17];
    const float* ss_win   = (const float*)d_in[18];
    const float* ss_wst   = (const float*)d_in[19];
    const float* ss_b     = (const float*)d_in[20];
    const float* ss_wout  = (const float*)d_in[21];
    const float* ss_bout  = (const float*)d_in[22];
    const float* dec_w1   = (const float*)d_in[23];
    const float* dec_b1   = (const float*)d_in[24];
    const float* dec_w2   = (const float*)d_in[25];
    const float* dec_b2   = (const float*)d_in[26];
    const float* pde_mix  = (const float*)d_in[27];

    static int smem_set = 0;
    if (!smem_set) {
        cudaFuncSetAttribute(gemm_mma, cudaFuncAttributeMaxDynamicSharedMemorySize, GSMEM);
        smem_set = 1;
    }

    build_A<<<Nn, 256>>>(node_emb);

    encoder_kernel<<<(Bb*Nn)/8, 256>>>(hist, tid_emb, diw_emb, t2f_w, t2f_b,
                                       enc_w1, enc_b1, enc_w2, enc_b2);

    for (int s = 0; s < NSTEPS; s++) {
        split_field_T<<<dim3(BF/32, Nn/32), 256>>>();
        gemm_mma<<<dim3(BF/128, Nn/128), 256, GSMEM>>>();
        step_kernel<<<(Bb*Nn)/256, 256>>>(pde_w1, pde_b1, pde_w2, pde_b2,
                                          ss_win, ss_wst, ss_b, ss_wout, ss_bout,
                                          pde_mix, s == 0);
    }

    decoder_kernel<<<(Bb*Nn)/8, 256>>>(dec_w1, dec_b1, dec_w2, dec_b2,
                                       (float*)d_out);
}

// round 6
// speedup vs baseline: 2.6673x; 1.2919x over previous
#include <cuda_runtime.h>
#include <cuda_fp16.h>
#include <math.h>
#include <cstdint>

#define Bb 64
#define Ll 12
#define Nn 4096
#define Cc 3
#define FDm 32
#define HDm 64
#define OUTD 12
#define TIDn 288
#define DIWn 7
#define TDm 16
#define NSTEPS 4
#define EMBm 10
#define BF (Bb*FDm)   // 2048

// Scratch (device globals)
__device__ float g_A[(size_t)Nn*Nn];                        // softmax scratch
__device__ float g_field[(size_t)Nn*BF];                    // field[n][b*32+f]
__device__ float g_state[(size_t)Nn*BF];
__device__ float g_AF[(size_t)Nn*BF];                       // A @ field (fp32)
__device__ __align__(16) __half g_Ahi[(size_t)Nn*Nn];       // A hi split [n][m]
__device__ __align__(16) __half g_Alo[(size_t)Nn*Nn];       // A lo split
__device__ __align__(16) __half g_FT [(size_t)BF*Nn];       // fieldT fp16 [j][m]

// ------------------------------ PTX helpers -------------------------------
__device__ __forceinline__ uint32_t smem_to_u32(const void* p) {
    uint32_t a;
    asm("{ .reg .u64 t; cvta.to.shared.u64 t, %1; cvt.u32.u64 %0, t; }"
        : "=r"(a) : "l"(p));
    return a;
}
__device__ __forceinline__ void cp16(uint32_t dst, const void* src) {
    asm volatile("cp.async.cg.shared.global [%0], [%1], 16;" :: "r"(dst), "l"(src));
}
#define CP_COMMIT() asm volatile("cp.async.commit_group;" ::: "memory")
#define CP_WAIT(n)  asm volatile("cp.async.wait_group %0;" :: "n"(n) : "memory")

__device__ __forceinline__ void ldsm4(uint32_t* r, uint32_t addr) {
    asm volatile("ldmatrix.sync.aligned.m8n8.x4.shared.b16 {%0,%1,%2,%3}, [%4];"
                 : "=r"(r[0]), "=r"(r[1]), "=r"(r[2]), "=r"(r[3]) : "r"(addr));
}
__device__ __forceinline__ void mma_f16(float* c, const uint32_t* a, const uint32_t* b) {
    asm volatile("mma.sync.aligned.m16n8k16.row.col.f32.f16.f16.f32 "
                 "{%0,%1,%2,%3}, {%4,%5,%6,%7}, {%8,%9}, {%0,%1,%2,%3};"
                 : "+f"(c[0]), "+f"(c[1]), "+f"(c[2]), "+f"(c[3])
                 : "r"(a[0]), "r"(a[1]), "r"(a[2]), "r"(a[3]), "r"(b[0]), "r"(b[1]));
}

// ---------------------------------------------------------------------------
// A = softmax(relu(node_emb @ node_emb^T)); writes fp16 hi/lo split.
// ---------------------------------------------------------------------------
__global__ void __launch_bounds__(256) build_A(const float* __restrict__ emb) {
    int n = blockIdx.x;
    int tid = threadIdx.x;
    __shared__ float en[EMBm];
    __shared__ float red[256];
    if (tid < EMBm) en[tid] = emb[n*EMBm + tid];
    __syncthreads();
    float* row = g_A + (size_t)n * Nn;

    float lmax = 0.f;
    for (int m = tid; m < Nn; m += 256) {
        float d = 0.f;
        #pragma unroll
        for (int k = 0; k < EMBm; k++) d = fmaf(en[k], emb[m*EMBm + k], d);
        d = fmaxf(d, 0.f);
        row[m] = d;
        lmax = fmaxf(lmax, d);
    }
    red[tid] = lmax; __syncthreads();
    for (int s = 128; s > 0; s >>= 1) {
        if (tid < s) red[tid] = fmaxf(red[tid], red[tid+s]);
        __syncthreads();
    }
    float mx = red[0];
    __syncthreads();

    float lsum = 0.f;
    for (int m = tid; m < Nn; m += 256) {
        float e = expf(row[m] - mx);
        row[m] = e;
        lsum += e;
    }
    red[tid] = lsum; __syncthreads();
    for (int s = 128; s > 0; s >>= 1) {
        if (tid < s) red[tid] += red[tid+s];
        __syncthreads();
    }
    float inv = 1.f / red[0];
    __syncthreads();
    for (int m = tid; m < Nn; m += 256) {
        float v = row[m] * inv;
        __half h = __float2half_rn(v);
        float lo = v - __half2float(h);
        g_Ahi[(size_t)n*Nn + m] = h;
        g_Alo[(size_t)n*Nn + m] = __float2half_rn(lo);
    }
}

// ---------------------------------------------------------------------------
// Transpose field to fp16: FT[j][m] = field[m][j]
// ---------------------------------------------------------------------------
__global__ void __launch_bounds__(256) split_field_T() {
    __shared__ float t[32][33];
    int j0 = blockIdx.x * 32;
    int n0 = blockIdx.y * 32;
    int tx = threadIdx.x & 31, ty = threadIdx.x >> 5;   // 32 x 8
    #pragma unroll
    for (int r = 0; r < 32; r += 8)
        t[ty + r][tx] = g_field[(size_t)(n0 + ty + r) * BF + j0 + tx];
    __syncthreads();
    #pragma unroll
    for (int r = 0; r < 32; r += 8) {
        float v = t[tx][ty + r];
        g_FT[(size_t)(j0 + ty + r) * Nn + n0 + tx] = __float2half_rn(v);
    }
}

// ---------------------------------------------------------------------------
// Encoder + temporal embedding. One warp per (b,n).
// ---------------------------------------------------------------------------
__global__ void __launch_bounds__(256) encoder_kernel(
    const float* __restrict__ hist,
    const float* __restrict__ tid_emb, const float* __restrict__ diw_emb,
    const float* __restrict__ t2f_w,   const float* __restrict__ t2f_b,
    const float* __restrict__ w1, const float* __restrict__ b1,
    const float* __restrict__ w2, const float* __restrict__ b2)
{
    __shared__ float s_w1[Ll*Cc*HDm];
    __shared__ float s_w2[HDm*FDm];
    __shared__ float s_t2f[2*TDm*FDm];
    __shared__ float s_b1[HDm];
    __shared__ float s_b2[FDm];
    __shared__ float s_t2fb[FDm];
    int tid = threadIdx.x;
    for (int i = tid; i < Ll*Cc*HDm; i += 256) s_w1[i] = w1[i];
    for (int i = tid; i < HDm*FDm;   i += 256) s_w2[i] = w2[i];
    for (int i = tid; i < 2*TDm*FDm; i += 256) s_t2f[i] = t2f_w[i];
    if (tid < HDm) s_b1[tid] = b1[tid];
    if (tid < FDm) { s_b2[tid] = b2[tid]; s_t2fb[tid] = t2f_b[tid]; }
    __syncthreads();

    int warp = (blockIdx.x * 256 + tid) >> 5;
    int lane = tid & 31;
    int n = warp & (Nn - 1);
    int b = warp >> 12;

    const float* hb = hist + ((size_t)b * Ll * Nn + n) * Cc;
    float x[Ll*Cc];
    #pragma unroll
    for (int l = 0; l < Ll; l++)
        #pragma unroll
        for (int c = 0; c < Cc; c++)
            x[l*Cc + c] = hb[(size_t)l * Nn * Cc + c];

    float h0 = s_b1[lane], h1 = s_b1[32 + lane];
    #pragma unroll
    for (int k = 0; k < Ll*Cc; k++) {
        h0 = fmaf(x[k], s_w1[k*HDm + lane],      h0);
        h1 = fmaf(x[k], s_w1[k*HDm + 32 + lane], h1);
    }
    h0 = fmaxf(h0, 0.f); h1 = fmaxf(h1, 0.f);

    float acc = s_b2[lane];
    #pragma unroll
    for (int hh = 0; hh < HDm; hh++) {
        float v = __shfl_sync(0xffffffffu, (hh < 32) ? h0 : h1, hh & 31);
        acc = fmaf(v, s_w2[hh*FDm + lane], acc);
    }

    float v1 = hb[(size_t)(Ll-1)*Nn*Cc + 1];
    float v2 = hb[(size_t)(Ll-1)*Nn*Cc + 2];
    int ti = (int)(v1 * (float)TIDn); ti = min(max(ti, 0), TIDn-1);
    int di = (int)(v2 * (float)DIWn); di = min(max(di, 0), DIWn-1);
    #pragma unroll
    for (int k = 0; k < TDm; k++)
        acc = fmaf(tid_emb[ti*TDm + k], s_t2f[k*FDm + lane], acc);
    #pragma unroll
    for (int k = 0; k < TDm; k++)
        acc = fmaf(diw_emb[di*TDm + k], s_t2f[(TDm + k)*FDm + lane], acc);
    acc += s_t2fb[lane];

    g_field[(size_t)n * BF + b*FDm + lane] = acc;
}

// ---------------------------------------------------------------------------
// Split-fp16 tensor-core GEMM via mma.sync: g_AF = A @ field
// M=4096, N=2048, K=4096. CTA 128x128xBK32, 8 warps (2x4), warp tile 64x32.
// D += Ahi*B + Alo*B  (fp32 accum). 3-stage cp.async pipeline, 2 CTAs/SM.
// ---------------------------------------------------------------------------
#define BKg 32
#define LDAe 40                       // padded row stride (halfs) = 80 B
#define TILE_BYTES (128*LDAe*2)       // 10240
#define STAGE_BYTES (3*TILE_BYTES)    // 30720 (Ahi, Alo, B)
#define NST 3
#define GSMEM (NST*STAGE_BYTES)       // 92160

__global__ void __launch_bounds__(256, 2) gemm_mma()
{
    extern __shared__ char smem[];
    uint32_t sbase = smem_to_u32(smem);
    int tid = threadIdx.x;
    int lane = tid & 31;
    int wid = tid >> 5;
    int bcol = blockIdx.x;    // 0..15
    int brow = blockIdx.y;    // 0..31

    const __half* Ahi = g_Ahi + (size_t)brow * 128 * Nn;
    const __half* Alo = g_Alo + (size_t)brow * 128 * Nn;
    const __half* Bt  = g_FT  + (size_t)bcol * 128 * Nn;

    // loader: thread t covers row r = t/2, 16-elem chunk c = (t&1)*16
    int lr = tid >> 1;
    int lc = (tid & 1) * 16;
    size_t goff = (size_t)lr * Nn + lc;
    uint32_t sdst = sbase + lr * (LDAe*2) + lc * 2;

    int warp_m = wid & 1;
    int warp_n = wid >> 1;
    int m_base = warp_m * 64;
    int n_base = warp_n * 32;

    float acc[4][4][4];
    #pragma unroll
    for (int i = 0; i < 4; i++)
        #pragma unroll
        for (int j = 0; j < 4; j++)
            #pragma unroll
            for (int q = 0; q < 4; q++) acc[i][j][q] = 0.f;

    uint32_t a_off[4];
    #pragma unroll
    for (int i = 0; i < 4; i++)
        a_off[i] = (m_base + i*16 + (lane & 15)) * (LDAe*2) + ((lane >> 4) * 8) * 2;
    uint32_t b_off[2];
    #pragma unroll
    for (int j = 0; j < 2; j++)
        b_off[j] = (n_base + j*16 + ((lane >> 4) << 3) + (lane & 7)) * (LDAe*2)
                 + (((lane >> 3) & 1) * 8) * 2;

    const int NIT = Nn / BKg;   // 128

    // prefetch stages 0 and 1
    #pragma unroll
    for (int p = 0; p < 2; p++) {
        uint32_t d = sdst + p * STAGE_BYTES;
        size_t g = goff + (size_t)p * BKg;
        cp16(d,                  Ahi + g); cp16(d + 16,                Ahi + g + 8);
        cp16(d + TILE_BYTES,     Alo + g); cp16(d + TILE_BYTES + 16,   Alo + g + 8);
        cp16(d + 2*TILE_BYTES,   Bt  + g); cp16(d + 2*TILE_BYTES + 16, Bt  + g + 8);
        CP_COMMIT();
    }

    int snxt = 2;  // stage index for (it+2)
    for (int it = 0; it < NIT; it++) {
        CP_WAIT(1);
        __syncthreads();

        // issue prefetch for it+2 (stage snxt), overlap with compute
        if (it + 2 < NIT) {
            uint32_t d = sdst + snxt * STAGE_BYTES;
            size_t g = goff + (size_t)(it + 2) * BKg;
            cp16(d,                  Ahi + g); cp16(d + 16,                Ahi + g + 8);
            cp16(d + TILE_BYTES,     Alo + g); cp16(d + TILE_BYTES + 16,   Alo + g + 8);
            cp16(d + 2*TILE_BYTES,   Bt  + g); cp16(d + 2*TILE_BYTES + 16, Bt  + g + 8);
        }
        CP_COMMIT();   // always commit (possibly empty) to keep group ledger aligned

        int scur = snxt + 1; if (scur >= NST) scur -= NST;  // = it % 3
        snxt = scur - 1 >= 0 ? scur - 1 : scur - 1 + NST;   // hmm avoid branches
        // (scur = it % NST; snxt for next iter = (it+3) % NST = scur... compute directly)
        scur = it % NST;
        snxt = scur;  // stage (it+3)%3 == it%3: after this iter, the freed stage is scur

        uint32_t st = sbase + scur * STAGE_BYTES;
        #pragma unroll
        for (int kk = 0; kk < 2; kk++) {
            uint32_t koff = kk * 16 * 2;
            uint32_t ahif[4][4], alof[4][4];
            #pragma unroll
            for (int i = 0; i < 4; i++) {
                uint32_t ad = st + a_off[i] + koff;
                ldsm4(ahif[i], ad);
                ldsm4(alof[i], ad + TILE_BYTES);
            }
            uint32_t bhf[2][4];
            #pragma unroll
            for (int j = 0; j < 2; j++)
                ldsm4(bhf[j], st + 2*TILE_BYTES + b_off[j] + koff);
            #pragma unroll
            for (int i = 0; i < 4; i++)
                #pragma unroll
                for (int na = 0; na < 4; na++) {
                    const uint32_t* bh = &bhf[na >> 1][(na & 1) * 2];
                    mma_f16(acc[i][na], ahif[i], bh);
                    mma_f16(acc[i][na], alof[i], bh);
                }
        }
    }

    __syncthreads();

    int grow0 = brow * 128 + m_base + (lane >> 2);
    int gcol0 = bcol * 128 + n_base + 2 * (lane & 3);
    #pragma unroll
    for (int i = 0; i < 4; i++) {
        #pragma unroll
        for (int na = 0; na < 4; na++) {
            float* p0 = g_AF + (size_t)(grow0 + i*16)     * BF + gcol0 + na*8;
            float* p1 = g_AF + (size_t)(grow0 + i*16 + 8) * BF + gcol0 + na*8;
            *(float2*)p0 = make_float2(acc[i][na][0], acc[i][na][1]);
            *(float2*)p1 = make_float2(acc[i][na][2], acc[i][na][3]);
        }
    }
}

// ---------------------------------------------------------------------------
// Per-step pointwise + small MLPs. Thread-per-point.
// ---------------------------------------------------------------------------
__global__ void __launch_bounds__(256) step_kernel(
    const float* __restrict__ pw1, const float* __restrict__ pb1,
    const float* __restrict__ pw2, const float* __restrict__ pb2,
    const float* __restrict__ win, const float* __restrict__ wst,
    const float* __restrict__ sb,  const float* __restrict__ wout,
    const float* __restrict__ bout, const float* __restrict__ pde_mix,
    int first)
{
    __shared__ float s_w1[FDm*HDm], s_w2[HDm*FDm];
    __shared__ float s_win[FDm*FDm], s_wst[FDm*FDm], s_wout[FDm*FDm];
    __shared__ float s_b1[HDm], s_b2[FDm], s_sb[FDm], s_bout[FDm];
    int tid = threadIdx.x;
    for (int i = tid; i < FDm*HDm; i += 256) { s_w1[i] = pw1[i]; s_w2[i] = pw2[i]; }
    for (int i = tid; i < FDm*FDm; i += 256) { s_win[i] = win[i]; s_wst[i] = wst[i]; s_wout[i] = wout[i]; }
    if (tid < HDm) s_b1[tid] = pb1[tid];
    if (tid < FDm) { s_b2[tid] = pb2[tid]; s_sb[tid] = sb[tid]; s_bout[tid] = bout[tid]; }
    __syncthreads();

    float alpha = 1.f / (1.f + expf(-pde_mix[0]));
    const float dtc = 1.f / NSTEPS;

    size_t p = (size_t)blockIdx.x * 256 + tid;
    float* fbase = g_field + p * FDm;
    const float* abase = g_AF + p * FDm;
    float* sbase_g = g_state + p * FDm;

    float x[FDm];
    #pragma unroll
    for (int i = 0; i < FDm/4; i++) *(float4*)&x[i*4] = *(const float4*)(fbase + i*4);

    float h[HDm];
    #pragma unroll
    for (int hh = 0; hh < HDm; hh++) h[hh] = s_b1[hh];
    #pragma unroll
    for (int k = 0; k < FDm; k++) {
        float xk = x[k];
        #pragma unroll
        for (int hh = 0; hh < HDm; hh++)
            h[hh] = fmaf(xk, s_w1[k*HDm + hh], h[hh]);
    }
    #pragma unroll
    for (int hh = 0; hh < HDm; hh++) h[hh] = fmaxf(h[hh], 0.f);

    float nf[FDm];
    #pragma unroll
    for (int f = 0; f < FDm; f++) nf[f] = s_b2[f];
    #pragma unroll
    for (int hh = 0; hh < HDm; hh++) {
        float hv = h[hh];
        #pragma unroll
        for (int f = 0; f < FDm; f++)
            nf[f] = fmaf(hv, s_w2[hh*FDm + f], nf[f]);
    }

    float fe[FDm];
    #pragma unroll
    for (int i = 0; i < FDm/4; i++) {
        float4 af4 = *(const float4*)(abase + i*4);
        float afv[4] = {af4.x, af4.y, af4.z, af4.w};
        #pragma unroll
        for (int q = 0; q < 4; q++) {
            int f = i*4 + q;
            fe[f] = x[f] + (alpha*(afv[q] - x[f]) + (1.f - alpha)*nf[f]) * dtc;
        }
    }

    float st[FDm];
    if (first) {
        #pragma unroll
        for (int f = 0; f < FDm; f++) st[f] = 0.f;
    } else {
        #pragma unroll
        for (int i = 0; i < FDm/4; i++) *(float4*)&st[i*4] = *(const float4*)(sbase_g + i*4);
    }

    float sa[FDm];
    #pragma unroll
    for (int f = 0; f < FDm; f++) sa[f] = s_sb[f];
    #pragma unroll
    for (int k = 0; k < FDm; k++) {
        float fk = fe[k], sk = st[k];
        #pragma unroll
        for (int f = 0; f < FDm; f++) {
            sa[f] = fmaf(fk, s_win[k*FDm + f], sa[f]);
            sa[f] = fmaf(sk, s_wst[k*FDm + f], sa[f]);
        }
    }
    float stn[FDm];
    #pragma unroll
    for (int f = 0; f < FDm; f++) stn[f] = tanhf(sa[f]);
    #pragma unroll
    for (int i = 0; i < FDm/4; i++) *(float4*)(sbase_g + i*4) = *(float4*)&stn[i*4];

    float fout[FDm];
    #pragma unroll
    for (int f = 0; f < FDm; f++) fout[f] = fe[f] + s_bout[f];
    #pragma unroll
    for (int k = 0; k < FDm; k++) {
        float sk = stn[k];
        #pragma unroll
        for (int f = 0; f < FDm; f++)
            fout[f] = fmaf(sk, s_wout[k*FDm + f], fout[f]);
    }
    #pragma unroll
    for (int i = 0; i < FDm/4; i++) *(float4*)(fbase + i*4) = *(float4*)&fout[i*4];
}

// ---------------------------------------------------------------------------
// Decoder. One warp per (b,n). out[(b*12+o)*4096 + n]
// ---------------------------------------------------------------------------
__global__ void __launch_bounds__(256) decoder_kernel(
    const float* __restrict__ w1, const float* __restrict__ b1,
    const float* __restrict__ w2, const float* __restrict__ b2,
    float* __restrict__ out)
{
    __shared__ float s_w1[FDm*HDm], s_w2[HDm*OUTD];
    __shared__ float s_b1[HDm], s_b2[OUTD];
    int tid = threadIdx.x;
    for (int i = tid; i < FDm*HDm;  i += 256) s_w1[i] = w1[i];
    for (int i = tid; i < HDm*OUTD; i += 256) s_w2[i] = w2[i];
    if (tid < HDm) s_b1[tid] = b1[tid];
    if (tid < OUTD) s_b2[tid] = b2[tid];
    __syncthreads();

    int warp = (blockIdx.x * 256 + tid) >> 5;
    int lane = tid & 31;
    int b = warp & 63;
    int n = warp >> 6;

    float fld = g_field[(size_t)n * BF + b*FDm + lane];
    float h0 = s_b1[lane], h1 = s_b1[32 + lane];
    #pragma unroll
    for (int k = 0; k < FDm; k++) {
        float fk = __shfl_sync(0xffffffffu, fld, k);
        h0 = fmaf(fk, s_w1[k*HDm + lane],      h0);
        h1 = fmaf(fk, s_w1[k*HDm + 32 + lane], h1);
    }
    h0 = fmaxf(h0, 0.f); h1 = fmaxf(h1, 0.f);

    float o = (lane < OUTD) ? s_b2[lane] : 0.f;
    #pragma unroll
    for (int hh = 0; hh < HDm; hh++) {
        float v = __shfl_sync(0xffffffffu, (hh < 32) ? h0 : h1, hh & 31);
        if (lane < OUTD) o = fmaf(v, s_w2[hh*OUTD + lane], o);
    }
    if (lane < OUTD)
        out[((size_t)b*OUTD + lane)*Nn + n] = o;
}

// ---------------------------------------------------------------------------
extern "C" void kernel_launch(void* const* d_in, const int* in_sizes, int n_in,
                              void* d_out, int out_size)
{
    const float* hist     = (const float*)d_in[0];
    const float* tid_emb  = (const float*)d_in[5];
    const float* diw_emb  = (const float*)d_in[6];
    const float* t2f_w    = (const float*)d_in[7];
    const float* t2f_b    = (const float*)d_in[8];
    const float* enc_w1   = (const float*)d_in[9];
    const float* enc_b1   = (const float*)d_in[10];
    const float* enc_w2   = (const float*)d_in[11];
    const float* enc_b2   = (const float*)d_in[12];
    const float* node_emb = (const float*)d_in[13];
    const float* pde_w1   = (const float*)d_in[14];
    const float* pde_b1   = (const float*)d_in[15];
    const float* pde_w2   = (const float*)d_in[16];
    const float* pde_b2   = (const float*)d_in[17];
    const float* ss_win   = (const float*)d_in[18];
    const float* ss_wst   = (const float*)d_in[19];
    const float* ss_b     = (const float*)d_in[20];
    const float* ss_wout  = (const float*)d_in[21];
    const float* ss_bout  = (const float*)d_in[22];
    const float* dec_w1   = (const float*)d_in[23];
    const float* dec_b1   = (const float*)d_in[24];
    const float* dec_w2   = (const float*)d_in[25];
    const float* dec_b2   = (const float*)d_in[26];
    const float* pde_mix  = (const float*)d_in[27];

    static int smem_set = 0;
    if (!smem_set) {
        cudaFuncSetAttribute(gemm_mma, cudaFuncAttributeMaxDynamicSharedMemorySize, GSMEM);
        smem_set = 1;
    }

    build_A<<<Nn, 256>>>(node_emb);

    encoder_kernel<<<(Bb*Nn)/8, 256>>>(hist, tid_emb, diw_emb, t2f_w, t2f_b,
                                       enc_w1, enc_b1, enc_w2, enc_b2);

    for (int s = 0; s < NSTEPS; s++) {
        split_field_T<<<dim3(BF/32, Nn/32), 256>>>();
        gemm_mma<<<dim3(BF/128, Nn/128), 256, GSMEM>>>();
        step_kernel<<<(Bb*Nn)/256, 256>>>(pde_w1, pde_b1, pde_w2, pde_b2,
                                          ss_win, ss_wst, ss_b, ss_wout, ss_bout,
                                          pde_mix, s == 0);
    }

    decoder_kernel<<<(Bb*Nn)/8, 256>>>(dec_w1, dec_b1, dec_w2, dec_b2,
                                       (float*)d_out);
}